// round 10
// baseline (speedup 1.0000x reference)
#include <cuda_runtime.h>
#include <cuda_bf16.h>
#include <math.h>
#include <cstdint>

// Problem constants
#define N_ 128
#define K_ 64
#define C_ 64
#define ROWS_ (N_ * K_)   // 8192

// Scratch (device globals: no allocation allowed)
__device__ float g_U [ROWS_ * C_];   // um * ug
__device__ float g_A [ROWS_ * C_];   // h @ Wb1[:C]  + bb1
__device__ float g_B [ROWS_ * C_];   // h @ Wb1[C:]
__device__ float g_Ag[ROWS_ * C_];   // h @ Wbg1[:C] + bbg1
__device__ float g_Bg[ROWS_ * C_];   // h @ Wbg1[C:]
// Precomputed bf16 hi/lo W image in exact main-kernel smem layout:
// [0,9216) Wb hi | [9216,18432) Wb lo | [18432,27648) Wg hi | [27648,36864) Wg lo
__device__ unsigned char g_Wimg[36864];

__device__ __forceinline__ float tanh_fast(float x) {
    float y;
    asm("tanh.approx.f32 %0, %1;" : "=f"(y) : "f"(x));
    return y;
}
__device__ __forceinline__ float fast_sigmoid(float x) {
    return __fdividef(1.0f, 1.0f + __expf(-x));
}

// pack two fp32 into bf16x2 (first arg -> low 16 bits)
__device__ __forceinline__ uint32_t pack_bf16x2(float lo, float hi) {
    uint32_t r;
    asm("cvt.rn.bf16x2.f32 %0, %1, %2;" : "=r"(r) : "f"(hi), "f"(lo));
    return r;
}

__device__ __forceinline__ uint32_t smem_to_u32(const void* p) {
    uint32_t a;
    asm("{ .reg .u64 t; cvta.to.shared.u64 t, %1; cvt.u32.u64 %0, t; }"
        : "=r"(a) : "l"(p));
    return a;
}

// warp-level bf16 HMMA, m16n8k16, row.col, f32 accumulate (base-target PTX)
__device__ __forceinline__ void mma16816(float acc[4], const uint32_t a[4],
                                         uint32_t b0, uint32_t b1) {
    asm volatile(
        "mma.sync.aligned.m16n8k16.row.col.f32.bf16.bf16.f32 "
        "{%0,%1,%2,%3}, {%4,%5,%6,%7}, {%8,%9}, {%0,%1,%2,%3};"
        : "+f"(acc[0]), "+f"(acc[1]), "+f"(acc[2]), "+f"(acc[3])
        : "r"(a[0]), "r"(a[1]), "r"(a[2]), "r"(a[3]), "r"(b0), "r"(b1));
}

__device__ __forceinline__ void ldm_x4(uint32_t r[4], uint32_t addr) {
    asm volatile(
        "ldmatrix.sync.aligned.m8n8.x4.shared.b16 {%0,%1,%2,%3}, [%4];"
        : "=r"(r[0]), "=r"(r[1]), "=r"(r[2]), "=r"(r[3]) : "r"(addr));
}

// named barriers (warp-uniform use only)
__device__ __forceinline__ void bar_sync(int id, int cnt) {
    asm volatile("bar.sync %0, %1;" :: "r"(id), "r"(cnt) : "memory");
}
__device__ __forceinline__ void bar_arrive(int id, int cnt) {
    asm volatile("bar.arrive %0, %1;" :: "r"(id), "r"(cnt) : "memory");
}

// ---------------------------------------------------------------------------
// Kernel 1 (unchanged from R9): blocks 0..127 compute h/U/A/B/Ag/Bg,
// warp-autonomous batched GEMV. Block 128 builds the bf16 W image.
// ---------------------------------------------------------------------------
#define PREP_SMEM_FLOATS (9 * 4096 + 16 * 512)

#define GEMV4(ACC, BUF, W, BIAS)                                              \
    {                                                                         \
        ACC[0] = BIAS; ACC[1] = BIAS; ACC[2] = BIAS; ACC[3] = BIAS;           \
        _Pragma("unroll 8")                                                   \
        for (int k2 = 0; k2 < 32; k2++) {                                     \
            const float2 w0 = *(const float2*)((W) + (2 * k2)     * 64 + c0); \
            const float2 w1 = *(const float2*)((W) + (2 * k2 + 1) * 64 + c0); \
            _Pragma("unroll")                                                 \
            for (int r4 = 0; r4 < 4; r4++) {                                  \
                const float2 v = *(const float2*)((BUF) + r4 * 64 + 2 * k2);  \
                ACC[r4].x = fmaf(v.x, w0.x, fmaf(v.y, w1.x, ACC[r4].x));      \
                ACC[r4].y = fmaf(v.x, w0.y, fmaf(v.y, w1.y, ACC[r4].y));      \
            }                                                                 \
        }                                                                     \
    }

__global__ __launch_bounds__(512)
void prep_kernel(const float* __restrict__ x,
                 const float* __restrict__ Wlin, const float* __restrict__ blin,
                 const float* __restrict__ Wu1,  const float* __restrict__ bu1,
                 const float* __restrict__ Wu2,  const float* __restrict__ bu2,
                 const float* __restrict__ Wug1, const float* __restrict__ bug1,
                 const float* __restrict__ Wug2, const float* __restrict__ bug2,
                 const float* __restrict__ Wb1,  const float* __restrict__ bb1,
                 const float* __restrict__ Wbg1, const float* __restrict__ bbg1,
                 const float* __restrict__ Wb2,  const float* __restrict__ Wbg2)
{
    const int tid = threadIdx.x;

    if (blockIdx.x == 128) {
        for (int idx = tid; idx < 4096; idx += 512) {
            const int k = idx >> 6, c = idx & 63;
            const int off = c * 144 + k * 2;
            {
                const float w = Wb2[idx];
                const __nv_bfloat16 h = __float2bfloat16(w);
                const __nv_bfloat16 l = __float2bfloat16(w - __bfloat162float(h));
                *(__nv_bfloat16*)(g_Wimg + off)        = h;
                *(__nv_bfloat16*)(g_Wimg + 9216 + off) = l;
            }
            {
                const float w = Wbg2[idx];
                const __nv_bfloat16 h = __float2bfloat16(w);
                const __nv_bfloat16 l = __float2bfloat16(w - __bfloat162float(h));
                *(__nv_bfloat16*)(g_Wimg + 18432 + off) = h;
                *(__nv_bfloat16*)(g_Wimg + 27648 + off) = l;
            }
        }
        return;
    }

    extern __shared__ float sm[];
    float* sWlin  = sm;
    float* sWu1   = sm + 4096;
    float* sWu2   = sm + 2 * 4096;
    float* sWug1  = sm + 3 * 4096;
    float* sWug2  = sm + 4 * 4096;
    float* sWb1a  = sm + 5 * 4096;
    float* sWb1b  = sm + 6 * 4096;
    float* sWbg1a = sm + 7 * 4096;
    float* sWbg1b = sm + 8 * 4096;
    float* bufs   = sm + 9 * 4096;   // [16 warps][2][4][64]

    for (int i = tid; i < 4096; i += 512) {
        sWlin[i]  = Wlin[i];
        sWu1[i]   = Wu1[i];
        sWu2[i]   = Wu2[i];
        sWug1[i]  = Wug1[i];
        sWug2[i]  = Wug2[i];
        sWb1a[i]  = Wb1[i];
        sWb1b[i]  = Wb1[4096 + i];
        sWbg1a[i] = Wbg1[i];
        sWbg1b[i] = Wbg1[4096 + i];
    }
    __syncthreads();

    const int w    = tid >> 5;
    const int lane = tid & 31;
    const int c0   = 2 * lane;
    float* buf0 = bufs + w * 512;
    float* buf1 = buf0 + 256;
    const int row0 = blockIdx.x * 64 + w * 4;

    const float2 blin2 = *(const float2*)(blin + c0);
    const float2 bu12  = *(const float2*)(bu1  + c0);
    const float2 bu22  = *(const float2*)(bu2  + c0);
    const float2 bug12 = *(const float2*)(bug1 + c0);
    const float2 bug22 = *(const float2*)(bug2 + c0);
    const float2 bb12  = *(const float2*)(bb1  + c0);
    const float2 bbg12 = *(const float2*)(bbg1 + c0);
    const float2 zero2 = make_float2(0.f, 0.f);

    #pragma unroll
    for (int r = 0; r < 4; r++)
        *(float2*)(buf0 + r * 64 + c0) = *(const float2*)(x + (row0 + r) * 64 + c0);
    __syncwarp();

    float2 hh[4]; GEMV4(hh, buf0, sWlin, blin2);
    __syncwarp();
    #pragma unroll
    for (int r = 0; r < 4; r++) *(float2*)(buf1 + r * 64 + c0) = hh[r];
    __syncwarp();

    float2 tt[4]; GEMV4(tt, buf1, sWu1, bu12);
    #pragma unroll
    for (int r = 0; r < 4; r++) {
        tt[r].x = tanh_fast(tt[r].x); tt[r].y = tanh_fast(tt[r].y);
    }
    __syncwarp();
    #pragma unroll
    for (int r = 0; r < 4; r++) *(float2*)(buf0 + r * 64 + c0) = tt[r];
    __syncwarp();

    float2 um[4]; GEMV4(um, buf0, sWu2, bu22);

    float2 t2[4]; GEMV4(t2, buf1, sWug1, bug12);
    #pragma unroll
    for (int r = 0; r < 4; r++) {
        t2[r].x = tanh_fast(t2[r].x); t2[r].y = tanh_fast(t2[r].y);
    }
    __syncwarp();
    #pragma unroll
    for (int r = 0; r < 4; r++) *(float2*)(buf0 + r * 64 + c0) = t2[r];
    __syncwarp();

    float2 ug[4]; GEMV4(ug, buf0, sWug2, bug22);
    #pragma unroll
    for (int r = 0; r < 4; r++) {
        float2 U;
        U.x = um[r].x * fast_sigmoid(ug[r].x);
        U.y = um[r].y * fast_sigmoid(ug[r].y);
        *(float2*)(g_U + (row0 + r) * 64 + c0) = U;
    }

    float2 fa[4], fb[4], fag[4], fbg[4];
    #pragma unroll
    for (int r = 0; r < 4; r++) { fa[r] = bb12; fb[r] = zero2; fag[r] = bbg12; fbg[r] = zero2; }
    #pragma unroll 4
    for (int k2 = 0; k2 < 32; k2++) {
        const int r0 = (2 * k2) * 64 + c0, r1 = (2 * k2 + 1) * 64 + c0;
        const float2 wa0 = *(const float2*)(sWb1a  + r0);
        const float2 wa1 = *(const float2*)(sWb1a  + r1);
        const float2 wb0 = *(const float2*)(sWb1b  + r0);
        const float2 wb1 = *(const float2*)(sWb1b  + r1);
        const float2 wc0 = *(const float2*)(sWbg1a + r0);
        const float2 wc1 = *(const float2*)(sWbg1a + r1);
        const float2 wd0 = *(const float2*)(sWbg1b + r0);
        const float2 wd1 = *(const float2*)(sWbg1b + r1);
        #pragma unroll
        for (int r = 0; r < 4; r++) {
            const float2 v = *(const float2*)(buf1 + r * 64 + 2 * k2);
            fa[r].x  = fmaf(v.x, wa0.x, fmaf(v.y, wa1.x, fa[r].x));
            fa[r].y  = fmaf(v.x, wa0.y, fmaf(v.y, wa1.y, fa[r].y));
            fb[r].x  = fmaf(v.x, wb0.x, fmaf(v.y, wb1.x, fb[r].x));
            fb[r].y  = fmaf(v.x, wb0.y, fmaf(v.y, wb1.y, fb[r].y));
            fag[r].x = fmaf(v.x, wc0.x, fmaf(v.y, wc1.x, fag[r].x));
            fag[r].y = fmaf(v.x, wc0.y, fmaf(v.y, wc1.y, fag[r].y));
            fbg[r].x = fmaf(v.x, wd0.x, fmaf(v.y, wd1.x, fbg[r].x));
            fbg[r].y = fmaf(v.x, wd0.y, fmaf(v.y, wd1.y, fbg[r].y));
        }
    }
    #pragma unroll
    for (int r = 0; r < 4; r++) {
        *(float2*)(g_A  + (row0 + r) * 64 + c0) = fa[r];
        *(float2*)(g_B  + (row0 + r) * 64 + c0) = fb[r];
        *(float2*)(g_Ag + (row0 + r) * 64 + c0) = fag[r];
        *(float2*)(g_Bg + (row0 + r) * 64 + c0) = fbg[r];
    }
}

// ---------------------------------------------------------------------------
// Kernel 2 (producer/consumer pipeline): 1024 blocks x 512 threads, 1 CTA/SM.
// Block = (n, 8 j's) = 4 tiles of 2 j's. Double-buffered A tiles.
// Warps 0-7 (producers): build bf16 hi/lo A tiles (tanh) into buf[t&1].
// Warps 8-15 (consumers): 32m x 32n MMA tiles, both paths, 3-pass split,
// gated epilogue + finalize. Named barriers: full0/1, empty0/1 (count 512).
// ---------------------------------------------------------------------------
#define WPITCH_B  144
// W image: WB_HI 0 | WB_LO 9216 | WG_HI 18432 | WG_LO 27648
#define OFF_W     0
#define OFF_BUF0  36864
#define BUF_SZ    73728   // AB_HI 0 | AB_LO 18432 | AG_HI 36864 | AG_LO 55296
#define OFF_BB2   184320
#define OFF_BBG2  184576
#define OFF_PART0 184832  // [8][32] floats
#define OFF_PART1 185856
#define MAIN_SMEM_BYTES 186880

#define BAR_FULL0  1
#define BAR_FULL1  2
#define BAR_EMPTY0 3
#define BAR_EMPTY1 4
#define BAR_CONS   5

__global__ __launch_bounds__(512, 1)
void main_kernel(const float* __restrict__ bb2, const float* __restrict__ bbg2,
                 float* __restrict__ out)
{
    extern __shared__ char smem[];
    const uint32_t sb = smem_to_u32(smem);
    const int tid  = threadIdx.x;
    const int wid  = tid >> 5;
    const int lane = tid & 31;
    const int n    = blockIdx.x >> 3;
    const int jg   = blockIdx.x & 7;

    // --- one-time: copy precomputed W image; biases ---
    {
        const uint4* wsrc = (const uint4*)g_Wimg;
        uint4* wdst = (uint4*)smem;
        for (int idx = tid; idx < 2304; idx += 512)
            wdst[idx] = wsrc[idx];
    }
    float* sbb2  = (float*)(smem + OFF_BB2);
    float* sbbg2 = (float*)(smem + OFF_BBG2);
    if (tid < 64) { sbb2[tid] = bb2[tid]; sbbg2[tid] = bbg2[tid]; }
    __syncthreads();

    if (wid < 8) {
        // ===================== PRODUCER (tid 0..255) =====================
        const int rbase = tid >> 4;              // 0..15
        const int ch    = tid & 15;              // float4-chunk within row
        const int q1    = ch >> 1;
        const int part1 = ch & 1;
        const int swz1  = ((rbase >> 3) & 1) * 4;

        // B rows are tile-invariant: cache in registers
        float4 Bb[4], Bg4[4];
        #pragma unroll
        for (int c = 0; c < 4; c++) {
            const int i = 16 * c + rbase;
            Bb[c]  = *(const float4*)(g_B  + n * 4096 + i * 64 + 4 * ch);
            Bg4[c] = *(const float4*)(g_Bg + n * 4096 + i * 64 + 4 * ch);
        }

        #pragma unroll 1
        for (int t = 0; t < 4; t++) {
            const int b = t & 1;
            if (t >= 2) bar_sync(BAR_EMPTY0 + b, 512);
            const int j0 = jg * 8 + 2 * t;
            char* bufbase = smem + OFF_BUF0 + b * BUF_SZ;

            #pragma unroll
            for (int p = 0; p < 2; p++) {
                const float* Asrc = (p ? g_Ag : g_A) + (n * 64 + j0) * 64 + 4 * ch;
                char* hiB = bufbase + p * 36864;
                char* loB = hiB + 18432;
                const float4 a0 = *(const float4*)(Asrc);
                const float4 a1 = *(const float4*)(Asrc + 64);
                #pragma unroll
                for (int c = 0; c < 4; c++) {
                    const int i = 16 * c + rbase;
                    const float4 bv = p ? Bg4[c] : Bb[c];
                    #pragma unroll
                    for (int jj = 0; jj < 2; jj++) {
                        const float4 a = jj ? a1 : a0;
                        const int row = jj * 64 + i;
                        const float t0 = tanh_fast(a.x + bv.x);
                        const float t1 = tanh_fast(a.y + bv.y);
                        const float t2 = tanh_fast(a.z + bv.z);
                        const float t3 = tanh_fast(a.w + bv.w);
                        const uint32_t h0 = pack_bf16x2(t0, t1);
                        const uint32_t h1 = pack_bf16x2(t2, t3);
                        const float hf0 = __uint_as_float(h0 << 16);
                        const float hf1 = __uint_as_float(h0 & 0xFFFF0000u);
                        const float hf2 = __uint_as_float(h1 << 16);
                        const float hf3 = __uint_as_float(h1 & 0xFFFF0000u);
                        const uint32_t l0 = pack_bf16x2(t0 - hf0, t1 - hf1);
                        const uint32_t l1 = pack_bf16x2(t2 - hf2, t3 - hf3);
                        const int boff = row * WPITCH_B + ((q1 ^ swz1) * 16) + part1 * 8;
                        *(uint2*)(hiB + boff) = make_uint2(h0, h1);
                        *(uint2*)(loB + boff) = make_uint2(l0, l1);
                    }
                }
            }
            bar_arrive(BAR_FULL0 + b, 512);
        }
    } else {
        // ===================== CONSUMER (tid 256..511) =====================
        const int ctid = tid - 256;
        const int cwid = ctid >> 5;              // 0..7
        const int gid  = lane >> 2;
        const int tig  = lane & 3;
        const int ms   = cwid & 3;               // m-strip
        const int nh   = cwid >> 2;              // n-half
        const int m0   = 32 * ms;
        const int cb   = 32 * nh;
        const int arow0 = m0 + (lane & 15);
        const int lsw   = ((lane >> 3) & 1) * 4;
        const int lch   = lane >> 4;

        #pragma unroll 1
        for (int t = 0; t < 4; t++) {
            const int b = t & 1;
            const int j0 = jg * 8 + 2 * t;
            bar_sync(BAR_FULL0 + b, 512);
            const uint32_t bufb = sb + OFF_BUF0 + (uint32_t)(b * BUF_SZ);

            float accb[2][4][4], accg[2][4][4];
            #pragma unroll
            for (int s = 0; s < 2; s++)
                #pragma unroll
                for (int nt = 0; nt < 4; nt++)
                    #pragma unroll
                    for (int r = 0; r < 4; r++) { accb[s][nt][r] = 0.f; accg[s][nt][r] = 0.f; }

            #pragma unroll
            for (int ks = 0; ks < 4; ks++) {
                const uint32_t chunk = (uint32_t)(((ks * 2 + lch) ^ lsw) * 16);
                uint32_t ah0[4], al0[4], ah1[4], al1[4];
                // ---- path b ----
                {
                    const uint32_t ad0 = bufb + (uint32_t)(arow0 * WPITCH_B) + chunk;
                    const uint32_t ad1 = ad0 + 16 * WPITCH_B;
                    ldm_x4(ah0, ad0);
                    ldm_x4(al0, ad0 + 18432);
                    ldm_x4(ah1, ad1);
                    ldm_x4(al1, ad1 + 18432);
                    #pragma unroll
                    for (int nt = 0; nt < 4; nt++) {
                        const char* wp = (const char*)smem + OFF_W +
                            (cb + nt * 8 + gid) * WPITCH_B + ks * 32 + 4 * tig;
                        const uint32_t h0 = *(const uint32_t*)(wp);
                        const uint32_t h1 = *(const uint32_t*)(wp + 16);
                        const uint32_t l0 = *(const uint32_t*)(wp + 9216);
                        const uint32_t l1 = *(const uint32_t*)(wp + 9216 + 16);
                        mma16816(accb[0][nt], ah0, h0, h1);
                        mma16816(accb[0][nt], ah0, l0, l1);
                        mma16816(accb[0][nt], al0, h0, h1);
                        mma16816(accb[1][nt], ah1, h0, h1);
                        mma16816(accb[1][nt], ah1, l0, l1);
                        mma16816(accb[1][nt], al1, h0, h1);
                    }
                }
                // ---- path g ----
                {
                    const uint32_t ad0 = bufb + 36864u + (uint32_t)(arow0 * WPITCH_B) + chunk;
                    const uint32_t ad1 = ad0 + 16 * WPITCH_B;
                    ldm_x4(ah0, ad0);
                    ldm_x4(al0, ad0 + 18432);
                    ldm_x4(ah1, ad1);
                    ldm_x4(al1, ad1 + 18432);
                    #pragma unroll
                    for (int nt = 0; nt < 4; nt++) {
                        const char* wp = (const char*)smem + OFF_W + 18432 +
                            (cb + nt * 8 + gid) * WPITCH_B + ks * 32 + 4 * tig;
                        const uint32_t h0 = *(const uint32_t*)(wp);
                        const uint32_t h1 = *(const uint32_t*)(wp + 16);
                        const uint32_t l0 = *(const uint32_t*)(wp + 9216);
                        const uint32_t l1 = *(const uint32_t*)(wp + 9216 + 16);
                        mma16816(accg[0][nt], ah0, h0, h1);
                        mma16816(accg[0][nt], ah0, l0, l1);
                        mma16816(accg[0][nt], al0, h0, h1);
                        mma16816(accg[1][nt], ah1, h0, h1);
                        mma16816(accg[1][nt], ah1, l0, l1);
                        mma16816(accg[1][nt], al1, h0, h1);
                    }
                }
            }
            // buffer b fully consumed
            bar_arrive(BAR_EMPTY0 + b, 512);

            // ---- epilogue: bias + gate + 32-row reduce ----
            float* partS = (float*)(smem + (b ? OFF_PART1 : OFF_PART0));
            #pragma unroll
            for (int nt = 0; nt < 4; nt++) {
                const int c0 = cb + nt * 8 + 2 * tig;
                const float2 bb = *(const float2*)(sbb2 + c0);
                const float2 gb = *(const float2*)(sbbg2 + c0);
                float p0 = 0.f, p1 = 0.f;
                #pragma unroll
                for (int s = 0; s < 2; s++) {
                    p0 += (accb[s][nt][0] + bb.x) * fast_sigmoid(accg[s][nt][0] + gb.x)
                        + (accb[s][nt][2] + bb.x) * fast_sigmoid(accg[s][nt][2] + gb.x);
                    p1 += (accb[s][nt][1] + bb.y) * fast_sigmoid(accg[s][nt][1] + gb.y)
                        + (accb[s][nt][3] + bb.y) * fast_sigmoid(accg[s][nt][3] + gb.y);
                }
                p0 += __shfl_xor_sync(0xFFFFFFFFu, p0, 4);
                p1 += __shfl_xor_sync(0xFFFFFFFFu, p1, 4);
                p0 += __shfl_xor_sync(0xFFFFFFFFu, p0, 8);
                p1 += __shfl_xor_sync(0xFFFFFFFFu, p1, 8);
                p0 += __shfl_xor_sync(0xFFFFFFFFu, p0, 16);
                p1 += __shfl_xor_sync(0xFFFFFFFFu, p1, 16);
                if (lane < 4)
                    *(float2*)(partS + cwid * 32 + nt * 8 + 2 * lane) = make_float2(p0, p1);
            }
            bar_sync(BAR_CONS, 256);

            // ---- finalize: sum 2 warp-partials per (jj,c), add U, store ----
            if (ctid < 128) {
                const int jj = ctid >> 6;
                const int c  = ctid & 63;
                const int w1 = (c >> 5) * 4 + 2 * jj;
                const int cl = c & 31;
                const float sum = partS[w1 * 32 + cl] + partS[(w1 + 1) * 32 + cl];
                const int o = (n * 64 + j0 + jj) * 64 + c;
                out[o] = g_U[o] + sum * (1.0f / 63.0f);
            }
            // safe: partS[b] rewritten only at t+2, after two all-consumer
            // full-barrier gates.
        }
    }
}

// ---------------------------------------------------------------------------
// launch
// ---------------------------------------------------------------------------
extern "C" void kernel_launch(void* const* d_in, const int* in_sizes, int n_in,
                              void* d_out, int out_size)
{
    const float* x    = (const float*)d_in[0];
    const float* Wlin = (const float*)d_in[1];
    const float* blin = (const float*)d_in[2];
    const float* Wu1  = (const float*)d_in[3];
    const float* bu1  = (const float*)d_in[4];
    const float* Wu2  = (const float*)d_in[5];
    const float* bu2  = (const float*)d_in[6];
    const float* Wug1 = (const float*)d_in[7];
    const float* bug1 = (const float*)d_in[8];
    const float* Wug2 = (const float*)d_in[9];
    const float* bug2 = (const float*)d_in[10];
    const float* Wb1  = (const float*)d_in[11];
    const float* bb1  = (const float*)d_in[12];
    const float* Wb2  = (const float*)d_in[13];
    const float* bb2  = (const float*)d_in[14];
    const float* Wbg1 = (const float*)d_in[15];
    const float* bbg1 = (const float*)d_in[16];
    const float* Wbg2 = (const float*)d_in[17];
    const float* bbg2 = (const float*)d_in[18];

    float* out = (float*)d_out;

    const int prep_smem = PREP_SMEM_FLOATS * (int)sizeof(float);   // 180224 B
    cudaFuncSetAttribute(prep_kernel, cudaFuncAttributeMaxDynamicSharedMemorySize, prep_smem);
    cudaFuncSetAttribute(main_kernel, cudaFuncAttributeMaxDynamicSharedMemorySize, MAIN_SMEM_BYTES);

    prep_kernel<<<129, 512, prep_smem>>>(x, Wlin, blin, Wu1, bu1, Wu2, bu2,
                                         Wug1, bug1, Wug2, bug2,
                                         Wb1, bb1, Wbg1, bbg1, Wb2, Wbg2);
    main_kernel<<<1024, 512, MAIN_SMEM_BYTES>>>(bb2, bbg2, out);
}

// round 11
// speedup vs baseline: 1.3277x; 1.3277x over previous
#include <cuda_runtime.h>
#include <cuda_fp16.h>
#include <math.h>
#include <cstdint>

// Problem constants
#define N_ 128
#define K_ 64
#define C_ 64
#define ROWS_ (N_ * K_)   // 8192

// Scratch (device globals: no allocation allowed)
__device__ float g_U [ROWS_ * C_];   // um * ug
__device__ float g_A [ROWS_ * C_];   // h @ Wb1[:C]  + bb1
__device__ float g_B [ROWS_ * C_];   // h @ Wb1[C:]
__device__ float g_Ag[ROWS_ * C_];   // h @ Wbg1[:C] + bbg1
__device__ float g_Bg[ROWS_ * C_];   // h @ Wbg1[C:]
// Precomputed fp16 hi/lo W image in exact main-kernel smem layout:
// [0,9216) Wb hi | [9216,18432) Wb lo | [18432,27648) Wg hi | [27648,36864) Wg lo
__device__ unsigned char g_Wimg[36864];

__device__ __forceinline__ float tanh_fast(float x) {
    float y;
    asm("tanh.approx.f32 %0, %1;" : "=f"(y) : "f"(x));
    return y;
}
__device__ __forceinline__ float fast_sigmoid(float x) {
    return __fdividef(1.0f, 1.0f + __expf(-x));
}

// pack two fp32 into f16x2 (first arg -> low 16 bits)
__device__ __forceinline__ uint32_t pack_f16x2(float lo, float hi) {
    uint32_t r;
    asm("cvt.rn.f16x2.f32 %0, %1, %2;" : "=r"(r) : "f"(hi), "f"(lo));
    return r;
}

__device__ __forceinline__ uint32_t smem_to_u32(const void* p) {
    uint32_t a;
    asm("{ .reg .u64 t; cvta.to.shared.u64 t, %1; cvt.u32.u64 %0, t; }"
        : "=r"(a) : "l"(p));
    return a;
}

// warp-level fp16 HMMA, m16n8k16, row.col, f32 accumulate (base-target PTX)
__device__ __forceinline__ void mma16816(float acc[4], const uint32_t a[4],
                                         uint32_t b0, uint32_t b1) {
    asm volatile(
        "mma.sync.aligned.m16n8k16.row.col.f32.f16.f16.f32 "
        "{%0,%1,%2,%3}, {%4,%5,%6,%7}, {%8,%9}, {%0,%1,%2,%3};"
        : "+f"(acc[0]), "+f"(acc[1]), "+f"(acc[2]), "+f"(acc[3])
        : "r"(a[0]), "r"(a[1]), "r"(a[2]), "r"(a[3]), "r"(b0), "r"(b1));
}

__device__ __forceinline__ void ldm_x4(uint32_t r[4], uint32_t addr) {
    asm volatile(
        "ldmatrix.sync.aligned.m8n8.x4.shared.b16 {%0,%1,%2,%3}, [%4];"
        : "=r"(r[0]), "=r"(r[1]), "=r"(r[2]), "=r"(r[3]) : "r"(addr));
}

// ---------------------------------------------------------------------------
// Kernel 1 (R9 structure): blocks 0..127 compute h/U/A/B/Ag/Bg,
// warp-autonomous batched GEMV. Block 128 builds the fp16 W image.
// ---------------------------------------------------------------------------
#define PREP_SMEM_FLOATS (9 * 4096 + 16 * 512)

#define GEMV4(ACC, BUF, W, BIAS)                                              \
    {                                                                         \
        ACC[0] = BIAS; ACC[1] = BIAS; ACC[2] = BIAS; ACC[3] = BIAS;           \
        _Pragma("unroll 8")                                                   \
        for (int k2 = 0; k2 < 32; k2++) {                                     \
            const float2 w0 = *(const float2*)((W) + (2 * k2)     * 64 + c0); \
            const float2 w1 = *(const float2*)((W) + (2 * k2 + 1) * 64 + c0); \
            _Pragma("unroll")                                                 \
            for (int r4 = 0; r4 < 4; r4++) {                                  \
                const float2 v = *(const float2*)((BUF) + r4 * 64 + 2 * k2);  \
                ACC[r4].x = fmaf(v.x, w0.x, fmaf(v.y, w1.x, ACC[r4].x));      \
                ACC[r4].y = fmaf(v.x, w0.y, fmaf(v.y, w1.y, ACC[r4].y));      \
            }                                                                 \
        }                                                                     \
    }

__global__ __launch_bounds__(512)
void prep_kernel(const float* __restrict__ x,
                 const float* __restrict__ Wlin, const float* __restrict__ blin,
                 const float* __restrict__ Wu1,  const float* __restrict__ bu1,
                 const float* __restrict__ Wu2,  const float* __restrict__ bu2,
                 const float* __restrict__ Wug1, const float* __restrict__ bug1,
                 const float* __restrict__ Wug2, const float* __restrict__ bug2,
                 const float* __restrict__ Wb1,  const float* __restrict__ bb1,
                 const float* __restrict__ Wbg1, const float* __restrict__ bbg1,
                 const float* __restrict__ Wb2,  const float* __restrict__ Wbg2)
{
    const int tid = threadIdx.x;

    if (blockIdx.x == 128) {
        for (int idx = tid; idx < 4096; idx += 512) {
            const int k = idx >> 6, c = idx & 63;
            const int off = c * 144 + k * 2;
            {
                const float w = Wb2[idx];
                const __half h = __float2half_rn(w);
                const __half l = __float2half_rn(w - __half2float(h));
                *(__half*)(g_Wimg + off)        = h;
                *(__half*)(g_Wimg + 9216 + off) = l;
            }
            {
                const float w = Wbg2[idx];
                const __half h = __float2half_rn(w);
                const __half l = __float2half_rn(w - __half2float(h));
                *(__half*)(g_Wimg + 18432 + off) = h;
                *(__half*)(g_Wimg + 27648 + off) = l;
            }
        }
        return;
    }

    extern __shared__ float sm[];
    float* sWlin  = sm;
    float* sWu1   = sm + 4096;
    float* sWu2   = sm + 2 * 4096;
    float* sWug1  = sm + 3 * 4096;
    float* sWug2  = sm + 4 * 4096;
    float* sWb1a  = sm + 5 * 4096;
    float* sWb1b  = sm + 6 * 4096;
    float* sWbg1a = sm + 7 * 4096;
    float* sWbg1b = sm + 8 * 4096;
    float* bufs   = sm + 9 * 4096;   // [16 warps][2][4][64]

    for (int i = tid; i < 4096; i += 512) {
        sWlin[i]  = Wlin[i];
        sWu1[i]   = Wu1[i];
        sWu2[i]   = Wu2[i];
        sWug1[i]  = Wug1[i];
        sWug2[i]  = Wug2[i];
        sWb1a[i]  = Wb1[i];
        sWb1b[i]  = Wb1[4096 + i];
        sWbg1a[i] = Wbg1[i];
        sWbg1b[i] = Wbg1[4096 + i];
    }
    __syncthreads();

    const int w    = tid >> 5;
    const int lane = tid & 31;
    const int c0   = 2 * lane;
    float* buf0 = bufs + w * 512;
    float* buf1 = buf0 + 256;
    const int row0 = blockIdx.x * 64 + w * 4;

    const float2 blin2 = *(const float2*)(blin + c0);
    const float2 bu12  = *(const float2*)(bu1  + c0);
    const float2 bu22  = *(const float2*)(bu2  + c0);
    const float2 bug12 = *(const float2*)(bug1 + c0);
    const float2 bug22 = *(const float2*)(bug2 + c0);
    const float2 bb12  = *(const float2*)(bb1  + c0);
    const float2 bbg12 = *(const float2*)(bbg1 + c0);
    const float2 zero2 = make_float2(0.f, 0.f);

    #pragma unroll
    for (int r = 0; r < 4; r++)
        *(float2*)(buf0 + r * 64 + c0) = *(const float2*)(x + (row0 + r) * 64 + c0);
    __syncwarp();

    float2 hh[4]; GEMV4(hh, buf0, sWlin, blin2);
    __syncwarp();
    #pragma unroll
    for (int r = 0; r < 4; r++) *(float2*)(buf1 + r * 64 + c0) = hh[r];
    __syncwarp();

    float2 tt[4]; GEMV4(tt, buf1, sWu1, bu12);
    #pragma unroll
    for (int r = 0; r < 4; r++) {
        tt[r].x = tanh_fast(tt[r].x); tt[r].y = tanh_fast(tt[r].y);
    }
    __syncwarp();
    #pragma unroll
    for (int r = 0; r < 4; r++) *(float2*)(buf0 + r * 64 + c0) = tt[r];
    __syncwarp();

    float2 um[4]; GEMV4(um, buf0, sWu2, bu22);

    float2 t2[4]; GEMV4(t2, buf1, sWug1, bug12);
    #pragma unroll
    for (int r = 0; r < 4; r++) {
        t2[r].x = tanh_fast(t2[r].x); t2[r].y = tanh_fast(t2[r].y);
    }
    __syncwarp();
    #pragma unroll
    for (int r = 0; r < 4; r++) *(float2*)(buf0 + r * 64 + c0) = t2[r];
    __syncwarp();

    float2 ug[4]; GEMV4(ug, buf0, sWug2, bug22);
    #pragma unroll
    for (int r = 0; r < 4; r++) {
        float2 U;
        U.x = um[r].x * fast_sigmoid(ug[r].x);
        U.y = um[r].y * fast_sigmoid(ug[r].y);
        *(float2*)(g_U + (row0 + r) * 64 + c0) = U;
    }

    float2 fa[4], fb[4], fag[4], fbg[4];
    #pragma unroll
    for (int r = 0; r < 4; r++) { fa[r] = bb12; fb[r] = zero2; fag[r] = bbg12; fbg[r] = zero2; }
    #pragma unroll 4
    for (int k2 = 0; k2 < 32; k2++) {
        const int r0 = (2 * k2) * 64 + c0, r1 = (2 * k2 + 1) * 64 + c0;
        const float2 wa0 = *(const float2*)(sWb1a  + r0);
        const float2 wa1 = *(const float2*)(sWb1a  + r1);
        const float2 wb0 = *(const float2*)(sWb1b  + r0);
        const float2 wb1 = *(const float2*)(sWb1b  + r1);
        const float2 wc0 = *(const float2*)(sWbg1a + r0);
        const float2 wc1 = *(const float2*)(sWbg1a + r1);
        const float2 wd0 = *(const float2*)(sWbg1b + r0);
        const float2 wd1 = *(const float2*)(sWbg1b + r1);
        #pragma unroll
        for (int r = 0; r < 4; r++) {
            const float2 v = *(const float2*)(buf1 + r * 64 + 2 * k2);
            fa[r].x  = fmaf(v.x, wa0.x, fmaf(v.y, wa1.x, fa[r].x));
            fa[r].y  = fmaf(v.x, wa0.y, fmaf(v.y, wa1.y, fa[r].y));
            fb[r].x  = fmaf(v.x, wb0.x, fmaf(v.y, wb1.x, fb[r].x));
            fb[r].y  = fmaf(v.x, wb0.y, fmaf(v.y, wb1.y, fb[r].y));
            fag[r].x = fmaf(v.x, wc0.x, fmaf(v.y, wc1.x, fag[r].x));
            fag[r].y = fmaf(v.x, wc0.y, fmaf(v.y, wc1.y, fag[r].y));
            fbg[r].x = fmaf(v.x, wd0.x, fmaf(v.y, wd1.x, fbg[r].x));
            fbg[r].y = fmaf(v.x, wd0.y, fmaf(v.y, wd1.y, fbg[r].y));
        }
    }
    #pragma unroll
    for (int r = 0; r < 4; r++) {
        *(float2*)(g_A  + (row0 + r) * 64 + c0) = fa[r];
        *(float2*)(g_B  + (row0 + r) * 64 + c0) = fb[r];
        *(float2*)(g_Ag + (row0 + r) * 64 + c0) = fag[r];
        *(float2*)(g_Bg + (row0 + r) * 64 + c0) = fbg[r];
    }
}

// ---------------------------------------------------------------------------
// Kernel 2 (R9 structure, fp16 2-pass): one block per (n, 4 j's) = 2 tiles of
// 2 j's. 2048 blocks x 256 threads, 2 CTAs/SM.
// Per tile: A[m][k] = tanh(A_j(m)[k] + B_i(m)[k]), fp16 single-precision A;
// W split hi/lo fp16 -> D = A@Wh + A@Wl. Warp tiles 32m x 32n, both paths.
// ---------------------------------------------------------------------------
#define WPITCH_B  144
// W image: WB_HI 0 | WB_LO 9216 | WG_HI 18432 | WG_LO 27648
#define OFF_AB    36864          // fp16 A tile, path b (18432 B)
#define OFF_AG    55296          // fp16 A tile, path g (18432 B)
#define OFF_BB2   73728
#define OFF_BBG2  73984
#define OFF_PART  74240          // [8][32] floats = 1024 B
#define MAIN_SMEM_BYTES 75264

__global__ __launch_bounds__(256, 2)
void main_kernel(const float* __restrict__ bb2, const float* __restrict__ bbg2,
                 float* __restrict__ out)
{
    extern __shared__ char smem[];
    const uint32_t sb = smem_to_u32(smem);
    const int tid  = threadIdx.x;
    const int wid  = tid >> 5;
    const int lane = tid & 31;
    const int gid  = lane >> 2;
    const int tig  = lane & 3;
    const int n    = blockIdx.x >> 4;
    const int jg   = blockIdx.x & 15;

    // --- one-time: copy precomputed W image (both paths, hi+lo) ---
    {
        const uint4* wsrc = (const uint4*)g_Wimg;
        uint4* wdst = (uint4*)smem;
        #pragma unroll
        for (int i = 0; i < 9; i++)
            wdst[tid + 256 * i] = wsrc[tid + 256 * i];
    }
    float* sbb2  = (float*)(smem + OFF_BB2);
    float* sbbg2 = (float*)(smem + OFF_BBG2);
    if (tid < 64) { sbb2[tid] = bb2[tid]; sbbg2[tid] = bbg2[tid]; }
    __syncthreads();

    // phase-1 mapping: (rbase, ch) — coalesced full-row loads
    const int rbase = tid >> 4;              // 0..15
    const int ch    = tid & 15;              // float4-chunk within row
    const int q1    = ch >> 1;
    const int part1 = ch & 1;
    const int swz1  = ((rbase >> 3) & 1) * 4;

    // MMA mapping: 32m x 32n warp tiles
    const int ms    = wid & 3;               // m-strip
    const int nh    = wid >> 2;               // n-half
    const int m0    = 32 * ms;
    const int cb    = 32 * nh;
    const int arow0 = m0 + (lane & 15);
    const int lsw   = ((lane >> 3) & 1) * 4;
    const int lch   = lane >> 4;

    float* partS = (float*)(smem + OFF_PART);

    for (int t = 0; t < 2; t++) {
        const int j0 = jg * 4 + 2 * t;

        // ---- phase 1: build fp16 A tiles (both paths), coalesced ----
        #pragma unroll
        for (int p = 0; p < 2; p++) {
            const float* Bsrc = (p ? g_Bg : g_B) + n * 4096;
            const float* Asrc = (p ? g_Ag : g_A) + (n * 64 + j0) * 64 + 4 * ch;
            char* hiB = smem + (p ? OFF_AG : OFF_AB);
            const float4 a0 = *(const float4*)(Asrc);
            const float4 a1 = *(const float4*)(Asrc + 64);
            #pragma unroll
            for (int c = 0; c < 4; c++) {
                const int i = 16 * c + rbase;
                const float4 b = *(const float4*)(Bsrc + i * 64 + 4 * ch);
                #pragma unroll
                for (int jj = 0; jj < 2; jj++) {
                    const float4 a = jj ? a1 : a0;
                    const int row = jj * 64 + i;
                    const float t0 = tanh_fast(a.x + b.x);
                    const float t1 = tanh_fast(a.y + b.y);
                    const float t2 = tanh_fast(a.z + b.z);
                    const float t3 = tanh_fast(a.w + b.w);
                    const uint32_t h0 = pack_f16x2(t0, t1);
                    const uint32_t h1 = pack_f16x2(t2, t3);
                    const int boff = row * WPITCH_B + ((q1 ^ swz1) * 16) + part1 * 8;
                    *(uint2*)(hiB + boff) = make_uint2(h0, h1);
                }
            }
        }
        __syncthreads();   // sync #1

        // ---- MMA: 32x32 warp tile, both paths, 2-pass W split ----
        float accb[2][4][4], accg[2][4][4];
        #pragma unroll
        for (int s = 0; s < 2; s++)
            #pragma unroll
            for (int nt = 0; nt < 4; nt++)
                #pragma unroll
                for (int r = 0; r < 4; r++) { accb[s][nt][r] = 0.f; accg[s][nt][r] = 0.f; }

        #pragma unroll
        for (int ks = 0; ks < 4; ks++) {
            const uint32_t chunk = (uint32_t)(((ks * 2 + lch) ^ lsw) * 16);
            uint32_t ah0[4], ah1[4];
            // ---- path b ----
            {
                const uint32_t ad0 = sb + OFF_AB + (uint32_t)(arow0 * WPITCH_B) + chunk;
                ldm_x4(ah0, ad0);
                ldm_x4(ah1, ad0 + 16 * WPITCH_B);
                #pragma unroll
                for (int nt = 0; nt < 4; nt++) {
                    const char* wp = (const char*)smem +
                        (cb + nt * 8 + gid) * WPITCH_B + ks * 32 + 4 * tig;
                    const uint32_t h0 = *(const uint32_t*)(wp);
                    const uint32_t h1 = *(const uint32_t*)(wp + 16);
                    const uint32_t l0 = *(const uint32_t*)(wp + 9216);
                    const uint32_t l1 = *(const uint32_t*)(wp + 9216 + 16);
                    mma16816(accb[0][nt], ah0, h0, h1);
                    mma16816(accb[0][nt], ah0, l0, l1);
                    mma16816(accb[1][nt], ah1, h0, h1);
                    mma16816(accb[1][nt], ah1, l0, l1);
                }
            }
            // ---- path g (reuse fragment registers) ----
            {
                const uint32_t ad0 = sb + OFF_AG + (uint32_t)(arow0 * WPITCH_B) + chunk;
                ldm_x4(ah0, ad0);
                ldm_x4(ah1, ad0 + 16 * WPITCH_B);
                #pragma unroll
                for (int nt = 0; nt < 4; nt++) {
                    const char* wp = (const char*)smem + 18432 +
                        (cb + nt * 8 + gid) * WPITCH_B + ks * 32 + 4 * tig;
                    const uint32_t h0 = *(const uint32_t*)(wp);
                    const uint32_t h1 = *(const uint32_t*)(wp + 16);
                    const uint32_t l0 = *(const uint32_t*)(wp + 9216);
                    const uint32_t l1 = *(const uint32_t*)(wp + 9216 + 16);
                    mma16816(accg[0][nt], ah0, h0, h1);
                    mma16816(accg[0][nt], ah0, l0, l1);
                    mma16816(accg[1][nt], ah1, h0, h1);
                    mma16816(accg[1][nt], ah1, l0, l1);
                }
            }
        }

        // ---- epilogue in registers: bias + gate + 32-row reduce ----
        #pragma unroll
        for (int nt = 0; nt < 4; nt++) {
            const int c0 = cb + nt * 8 + 2 * tig;
            const float2 bb = *(const float2*)(sbb2 + c0);
            const float2 gb = *(const float2*)(sbbg2 + c0);
            float p0 = 0.f, p1 = 0.f;
            #pragma unroll
            for (int s = 0; s < 2; s++) {
                p0 += (accb[s][nt][0] + bb.x) * fast_sigmoid(accg[s][nt][0] + gb.x)
                    + (accb[s][nt][2] + bb.x) * fast_sigmoid(accg[s][nt][2] + gb.x);
                p1 += (accb[s][nt][1] + bb.y) * fast_sigmoid(accg[s][nt][1] + gb.y)
                    + (accb[s][nt][3] + bb.y) * fast_sigmoid(accg[s][nt][3] + gb.y);
            }
            p0 += __shfl_xor_sync(0xFFFFFFFFu, p0, 4);
            p1 += __shfl_xor_sync(0xFFFFFFFFu, p1, 4);
            p0 += __shfl_xor_sync(0xFFFFFFFFu, p0, 8);
            p1 += __shfl_xor_sync(0xFFFFFFFFu, p1, 8);
            p0 += __shfl_xor_sync(0xFFFFFFFFu, p0, 16);
            p1 += __shfl_xor_sync(0xFFFFFFFFu, p1, 16);
            if (lane < 4)   // lanes 0..3: gid=0, tig=lane
                *(float2*)(partS + wid * 32 + nt * 8 + 2 * lane) = make_float2(p0, p1);
        }
        __syncthreads();   // sync #2

        // ---- finalize: sum 2 warp-partials per (jj,c), add U, store ----
        if (tid < 128) {
            const int jj = tid >> 6;
            const int c  = tid & 63;
            const int w1 = (c >> 5) * 4 + 2 * jj;   // ms = 2jj, nh = c>>5
            const int cl = c & 31;
            const float sum = partS[w1 * 32 + cl] + partS[(w1 + 1) * 32 + cl];
            const int o = (n * 64 + j0 + jj) * 64 + c;
            out[o] = g_U[o] + sum * (1.0f / 63.0f);
        }
        // no extra sync: partS(t+1) writes occur only after sync #1 of t+1,
        // which all finalize threads must reach first.
    }
}

// ---------------------------------------------------------------------------
// launch
// ---------------------------------------------------------------------------
extern "C" void kernel_launch(void* const* d_in, const int* in_sizes, int n_in,
                              void* d_out, int out_size)
{
    const float* x    = (const float*)d_in[0];
    const float* Wlin = (const float*)d_in[1];
    const float* blin = (const float*)d_in[2];
    const float* Wu1  = (const float*)d_in[3];
    const float* bu1  = (const float*)d_in[4];
    const float* Wu2  = (const float*)d_in[5];
    const float* bu2  = (const float*)d_in[6];
    const float* Wug1 = (const float*)d_in[7];
    const float* bug1 = (const float*)d_in[8];
    const float* Wug2 = (const float*)d_in[9];
    const float* bug2 = (const float*)d_in[10];
    const float* Wb1  = (const float*)d_in[11];
    const float* bb1  = (const float*)d_in[12];
    const float* Wb2  = (const float*)d_in[13];
    const float* bb2  = (const float*)d_in[14];
    const float* Wbg1 = (const float*)d_in[15];
    const float* bbg1 = (const float*)d_in[16];
    const float* Wbg2 = (const float*)d_in[17];
    const float* bbg2 = (const float*)d_in[18];

    float* out = (float*)d_out;

    const int prep_smem = PREP_SMEM_FLOATS * (int)sizeof(float);   // 180224 B
    cudaFuncSetAttribute(prep_kernel, cudaFuncAttributeMaxDynamicSharedMemorySize, prep_smem);
    cudaFuncSetAttribute(main_kernel, cudaFuncAttributeMaxDynamicSharedMemorySize, MAIN_SMEM_BYTES);

    prep_kernel<<<129, 512, prep_smem>>>(x, Wlin, blin, Wu1, bu1, Wu2, bu2,
                                         Wug1, bug1, Wug2, bug2,
                                         Wb1, bb1, Wbg1, bbg1, Wb2, Wbg2);
    main_kernel<<<2048, 256, MAIN_SMEM_BYTES>>>(bb2, bbg2, out);
}

// round 12
// speedup vs baseline: 1.4078x; 1.0604x over previous
#include <cuda_runtime.h>
#include <cuda_fp16.h>
#include <math.h>
#include <cstdint>

// Problem constants
#define N_ 128
#define K_ 64
#define C_ 64
#define ROWS_ (N_ * K_)   // 8192

// Scratch (device globals: no allocation allowed)
__device__ float g_U [ROWS_ * C_];   // um * ug
__device__ float g_A [ROWS_ * C_];   // h @ Wb1[:C]  + bb1
__device__ float g_B [ROWS_ * C_];   // h @ Wb1[C:]
__device__ float g_Ag[ROWS_ * C_];   // h @ Wbg1[:C] + bbg1
__device__ float g_Bg[ROWS_ * C_];   // h @ Wbg1[C:]
// Precomputed fp16 hi/lo W image in exact main-kernel smem layout:
// [0,9216) Wb hi | [9216,18432) Wb lo | [18432,27648) Wg hi | [27648,36864) Wg lo
__device__ unsigned char g_Wimg[36864];

__device__ __forceinline__ float tanh_fast(float x) {
    float y;
    asm("tanh.approx.f32 %0, %1;" : "=f"(y) : "f"(x));
    return y;
}
__device__ __forceinline__ uint32_t tanh_f16x2(uint32_t x) {
    uint32_t y;
    asm("tanh.approx.f16x2 %0, %1;" : "=r"(y) : "r"(x));
    return y;
}
__device__ __forceinline__ float fast_sigmoid(float x) {
    return __fdividef(1.0f, 1.0f + __expf(-x));
}
// 1-MUFU sigmoid: 0.5 + 0.5*tanh(x/2)
__device__ __forceinline__ float sigmoid_t(float x) {
    return fmaf(tanh_fast(0.5f * x), 0.5f, 0.5f);
}

// pack two fp32 into f16x2 (first arg -> low 16 bits)
__device__ __forceinline__ uint32_t pack_f16x2(float lo, float hi) {
    uint32_t r;
    asm("cvt.rn.f16x2.f32 %0, %1, %2;" : "=r"(r) : "f"(hi), "f"(lo));
    return r;
}

__device__ __forceinline__ uint32_t smem_to_u32(const void* p) {
    uint32_t a;
    asm("{ .reg .u64 t; cvta.to.shared.u64 t, %1; cvt.u32.u64 %0, t; }"
        : "=r"(a) : "l"(p));
    return a;
}

// warp-level fp16 HMMA, m16n8k16, row.col, f32 accumulate (base-target PTX)
__device__ __forceinline__ void mma16816(float acc[4], const uint32_t a[4],
                                         uint32_t b0, uint32_t b1) {
    asm volatile(
        "mma.sync.aligned.m16n8k16.row.col.f32.f16.f16.f32 "
        "{%0,%1,%2,%3}, {%4,%5,%6,%7}, {%8,%9}, {%0,%1,%2,%3};"
        : "+f"(acc[0]), "+f"(acc[1]), "+f"(acc[2]), "+f"(acc[3])
        : "r"(a[0]), "r"(a[1]), "r"(a[2]), "r"(a[3]), "r"(b0), "r"(b1));
}

__device__ __forceinline__ void ldm_x4(uint32_t r[4], uint32_t addr) {
    asm volatile(
        "ldmatrix.sync.aligned.m8n8.x4.shared.b16 {%0,%1,%2,%3}, [%4];"
        : "=r"(r[0]), "=r"(r[1]), "=r"(r[2]), "=r"(r[3]) : "r"(addr));
}

// ---------------------------------------------------------------------------
// Kernel 1 (unchanged from R11): blocks 0..127 compute h/U/A/B/Ag/Bg,
// warp-autonomous batched GEMV. Block 128 builds the fp16 W image.
// ---------------------------------------------------------------------------
#define PREP_SMEM_FLOATS (9 * 4096 + 16 * 512)

#define GEMV4(ACC, BUF, W, BIAS)                                              \
    {                                                                         \
        ACC[0] = BIAS; ACC[1] = BIAS; ACC[2] = BIAS; ACC[3] = BIAS;           \
        _Pragma("unroll 8")                                                   \
        for (int k2 = 0; k2 < 32; k2++) {                                     \
            const float2 w0 = *(const float2*)((W) + (2 * k2)     * 64 + c0); \
            const float2 w1 = *(const float2*)((W) + (2 * k2 + 1) * 64 + c0); \
            _Pragma("unroll")                                                 \
            for (int r4 = 0; r4 < 4; r4++) {                                  \
                const float2 v = *(const float2*)((BUF) + r4 * 64 + 2 * k2);  \
                ACC[r4].x = fmaf(v.x, w0.x, fmaf(v.y, w1.x, ACC[r4].x));      \
                ACC[r4].y = fmaf(v.x, w0.y, fmaf(v.y, w1.y, ACC[r4].y));      \
            }                                                                 \
        }                                                                     \
    }

__global__ __launch_bounds__(512)
void prep_kernel(const float* __restrict__ x,
                 const float* __restrict__ Wlin, const float* __restrict__ blin,
                 const float* __restrict__ Wu1,  const float* __restrict__ bu1,
                 const float* __restrict__ Wu2,  const float* __restrict__ bu2,
                 const float* __restrict__ Wug1, const float* __restrict__ bug1,
                 const float* __restrict__ Wug2, const float* __restrict__ bug2,
                 const float* __restrict__ Wb1,  const float* __restrict__ bb1,
                 const float* __restrict__ Wbg1, const float* __restrict__ bbg1,
                 const float* __restrict__ Wb2,  const float* __restrict__ Wbg2)
{
    const int tid = threadIdx.x;

    if (blockIdx.x == 128) {
        for (int idx = tid; idx < 4096; idx += 512) {
            const int k = idx >> 6, c = idx & 63;
            const int off = c * 144 + k * 2;
            {
                const float w = Wb2[idx];
                const __half h = __float2half_rn(w);
                const __half l = __float2half_rn(w - __half2float(h));
                *(__half*)(g_Wimg + off)        = h;
                *(__half*)(g_Wimg + 9216 + off) = l;
            }
            {
                const float w = Wbg2[idx];
                const __half h = __float2half_rn(w);
                const __half l = __float2half_rn(w - __half2float(h));
                *(__half*)(g_Wimg + 18432 + off) = h;
                *(__half*)(g_Wimg + 27648 + off) = l;
            }
        }
        return;
    }

    extern __shared__ float sm[];
    float* sWlin  = sm;
    float* sWu1   = sm + 4096;
    float* sWu2   = sm + 2 * 4096;
    float* sWug1  = sm + 3 * 4096;
    float* sWug2  = sm + 4 * 4096;
    float* sWb1a  = sm + 5 * 4096;
    float* sWb1b  = sm + 6 * 4096;
    float* sWbg1a = sm + 7 * 4096;
    float* sWbg1b = sm + 8 * 4096;
    float* bufs   = sm + 9 * 4096;   // [16 warps][2][4][64]

    for (int i = tid; i < 4096; i += 512) {
        sWlin[i]  = Wlin[i];
        sWu1[i]   = Wu1[i];
        sWu2[i]   = Wu2[i];
        sWug1[i]  = Wug1[i];
        sWug2[i]  = Wug2[i];
        sWb1a[i]  = Wb1[i];
        sWb1b[i]  = Wb1[4096 + i];
        sWbg1a[i] = Wbg1[i];
        sWbg1b[i] = Wbg1[4096 + i];
    }
    __syncthreads();

    const int w    = tid >> 5;
    const int lane = tid & 31;
    const int c0   = 2 * lane;
    float* buf0 = bufs + w * 512;
    float* buf1 = buf0 + 256;
    const int row0 = blockIdx.x * 64 + w * 4;

    const float2 blin2 = *(const float2*)(blin + c0);
    const float2 bu12  = *(const float2*)(bu1  + c0);
    const float2 bu22  = *(const float2*)(bu2  + c0);
    const float2 bug12 = *(const float2*)(bug1 + c0);
    const float2 bug22 = *(const float2*)(bug2 + c0);
    const float2 bb12  = *(const float2*)(bb1  + c0);
    const float2 bbg12 = *(const float2*)(bbg1 + c0);
    const float2 zero2 = make_float2(0.f, 0.f);

    #pragma unroll
    for (int r = 0; r < 4; r++)
        *(float2*)(buf0 + r * 64 + c0) = *(const float2*)(x + (row0 + r) * 64 + c0);
    __syncwarp();

    float2 hh[4]; GEMV4(hh, buf0, sWlin, blin2);
    __syncwarp();
    #pragma unroll
    for (int r = 0; r < 4; r++) *(float2*)(buf1 + r * 64 + c0) = hh[r];
    __syncwarp();

    float2 tt[4]; GEMV4(tt, buf1, sWu1, bu12);
    #pragma unroll
    for (int r = 0; r < 4; r++) {
        tt[r].x = tanh_fast(tt[r].x); tt[r].y = tanh_fast(tt[r].y);
    }
    __syncwarp();
    #pragma unroll
    for (int r = 0; r < 4; r++) *(float2*)(buf0 + r * 64 + c0) = tt[r];
    __syncwarp();

    float2 um[4]; GEMV4(um, buf0, sWu2, bu22);

    float2 t2[4]; GEMV4(t2, buf1, sWug1, bug12);
    #pragma unroll
    for (int r = 0; r < 4; r++) {
        t2[r].x = tanh_fast(t2[r].x); t2[r].y = tanh_fast(t2[r].y);
    }
    __syncwarp();
    #pragma unroll
    for (int r = 0; r < 4; r++) *(float2*)(buf0 + r * 64 + c0) = t2[r];
    __syncwarp();

    float2 ug[4]; GEMV4(ug, buf0, sWug2, bug22);
    #pragma unroll
    for (int r = 0; r < 4; r++) {
        float2 U;
        U.x = um[r].x * fast_sigmoid(ug[r].x);
        U.y = um[r].y * fast_sigmoid(ug[r].y);
        *(float2*)(g_U + (row0 + r) * 64 + c0) = U;
    }

    float2 fa[4], fb[4], fag[4], fbg[4];
    #pragma unroll
    for (int r = 0; r < 4; r++) { fa[r] = bb12; fb[r] = zero2; fag[r] = bbg12; fbg[r] = zero2; }
    #pragma unroll 4
    for (int k2 = 0; k2 < 32; k2++) {
        const int r0 = (2 * k2) * 64 + c0, r1 = (2 * k2 + 1) * 64 + c0;
        const float2 wa0 = *(const float2*)(sWb1a  + r0);
        const float2 wa1 = *(const float2*)(sWb1a  + r1);
        const float2 wb0 = *(const float2*)(sWb1b  + r0);
        const float2 wb1 = *(const float2*)(sWb1b  + r1);
        const float2 wc0 = *(const float2*)(sWbg1a + r0);
        const float2 wc1 = *(const float2*)(sWbg1a + r1);
        const float2 wd0 = *(const float2*)(sWbg1b + r0);
        const float2 wd1 = *(const float2*)(sWbg1b + r1);
        #pragma unroll
        for (int r = 0; r < 4; r++) {
            const float2 v = *(const float2*)(buf1 + r * 64 + 2 * k2);
            fa[r].x  = fmaf(v.x, wa0.x, fmaf(v.y, wa1.x, fa[r].x));
            fa[r].y  = fmaf(v.x, wa0.y, fmaf(v.y, wa1.y, fa[r].y));
            fb[r].x  = fmaf(v.x, wb0.x, fmaf(v.y, wb1.x, fb[r].x));
            fb[r].y  = fmaf(v.x, wb0.y, fmaf(v.y, wb1.y, fb[r].y));
            fag[r].x = fmaf(v.x, wc0.x, fmaf(v.y, wc1.x, fag[r].x));
            fag[r].y = fmaf(v.x, wc0.y, fmaf(v.y, wc1.y, fag[r].y));
            fbg[r].x = fmaf(v.x, wd0.x, fmaf(v.y, wd1.x, fbg[r].x));
            fbg[r].y = fmaf(v.x, wd0.y, fmaf(v.y, wd1.y, fbg[r].y));
        }
    }
    #pragma unroll
    for (int r = 0; r < 4; r++) {
        *(float2*)(g_A  + (row0 + r) * 64 + c0) = fa[r];
        *(float2*)(g_B  + (row0 + r) * 64 + c0) = fb[r];
        *(float2*)(g_Ag + (row0 + r) * 64 + c0) = fag[r];
        *(float2*)(g_Bg + (row0 + r) * 64 + c0) = fbg[r];
    }
}

// ---------------------------------------------------------------------------
// Kernel 2 (R11 structure, MUFU-halved): one block per (n, 4 j's) = 2 tiles
// of 2 j's. 2048 blocks x 256 threads, 2 CTAs/SM.
// Phase 1 uses tanh.approx.f16x2 (2 values/MUFU, output pre-packed).
// Epilogue sigmoid via tanh.approx.f32 (1 MUFU).
// ---------------------------------------------------------------------------
#define WPITCH_B  144
// W image: WB_HI 0 | WB_LO 9216 | WG_HI 18432 | WG_LO 27648
#define OFF_AB    36864          // fp16 A tile, path b (18432 B)
#define OFF_AG    55296          // fp16 A tile, path g (18432 B)
#define OFF_BB2   73728
#define OFF_BBG2  73984
#define OFF_PART  74240          // [8][32] floats = 1024 B
#define MAIN_SMEM_BYTES 75264

__global__ __launch_bounds__(256, 2)
void main_kernel(const float* __restrict__ bb2, const float* __restrict__ bbg2,
                 float* __restrict__ out)
{
    extern __shared__ char smem[];
    const uint32_t sb = smem_to_u32(smem);
    const int tid  = threadIdx.x;
    const int wid  = tid >> 5;
    const int lane = tid & 31;
    const int gid  = lane >> 2;
    const int tig  = lane & 3;
    const int n    = blockIdx.x >> 4;
    const int jg   = blockIdx.x & 15;

    // --- one-time: copy precomputed W image (both paths, hi+lo) ---
    {
        const uint4* wsrc = (const uint4*)g_Wimg;
        uint4* wdst = (uint4*)smem;
        #pragma unroll
        for (int i = 0; i < 9; i++)
            wdst[tid + 256 * i] = wsrc[tid + 256 * i];
    }
    float* sbb2  = (float*)(smem + OFF_BB2);
    float* sbbg2 = (float*)(smem + OFF_BBG2);
    if (tid < 64) { sbb2[tid] = bb2[tid]; sbbg2[tid] = bbg2[tid]; }
    __syncthreads();

    // phase-1 mapping: (rbase, ch) — coalesced full-row loads
    const int rbase = tid >> 4;              // 0..15
    const int ch    = tid & 15;              // float4-chunk within row
    const int q1    = ch >> 1;
    const int part1 = ch & 1;
    const int swz1  = ((rbase >> 3) & 1) * 4;

    // MMA mapping: 32m x 32n warp tiles
    const int ms    = wid & 3;               // m-strip
    const int nh    = wid >> 2;              // n-half
    const int m0    = 32 * ms;
    const int cb    = 32 * nh;
    const int arow0 = m0 + (lane & 15);
    const int lsw   = ((lane >> 3) & 1) * 4;
    const int lch   = lane >> 4;

    float* partS = (float*)(smem + OFF_PART);

    for (int t = 0; t < 2; t++) {
        const int j0 = jg * 4 + 2 * t;

        // ---- phase 1: build fp16 A tiles (both paths); f16x2 tanh ----
        #pragma unroll
        for (int p = 0; p < 2; p++) {
            const float* Bsrc = (p ? g_Bg : g_B) + n * 4096;
            const float* Asrc = (p ? g_Ag : g_A) + (n * 64 + j0) * 64 + 4 * ch;
            char* hiB = smem + (p ? OFF_AG : OFF_AB);
            const float4 a0 = *(const float4*)(Asrc);
            const float4 a1 = *(const float4*)(Asrc + 64);
            #pragma unroll
            for (int c = 0; c < 4; c++) {
                const int i = 16 * c + rbase;
                const float4 b = *(const float4*)(Bsrc + i * 64 + 4 * ch);
                #pragma unroll
                for (int jj = 0; jj < 2; jj++) {
                    const float4 a = jj ? a1 : a0;
                    const int row = jj * 64 + i;
                    const uint32_t h0 = tanh_f16x2(pack_f16x2(a.x + b.x, a.y + b.y));
                    const uint32_t h1 = tanh_f16x2(pack_f16x2(a.z + b.z, a.w + b.w));
                    const int boff = row * WPITCH_B + ((q1 ^ swz1) * 16) + part1 * 8;
                    *(uint2*)(hiB + boff) = make_uint2(h0, h1);
                }
            }
        }
        __syncthreads();   // sync #1

        // ---- MMA: 32x32 warp tile, both paths, 2-pass W split ----
        float accb[2][4][4], accg[2][4][4];
        #pragma unroll
        for (int s = 0; s < 2; s++)
            #pragma unroll
            for (int nt = 0; nt < 4; nt++)
                #pragma unroll
                for (int r = 0; r < 4; r++) { accb[s][nt][r] = 0.f; accg[s][nt][r] = 0.f; }

        #pragma unroll
        for (int ks = 0; ks < 4; ks++) {
            const uint32_t chunk = (uint32_t)(((ks * 2 + lch) ^ lsw) * 16);
            uint32_t ah0[4], ah1[4];
            // ---- path b ----
            {
                const uint32_t ad0 = sb + OFF_AB + (uint32_t)(arow0 * WPITCH_B) + chunk;
                ldm_x4(ah0, ad0);
                ldm_x4(ah1, ad0 + 16 * WPITCH_B);
                #pragma unroll
                for (int nt = 0; nt < 4; nt++) {
                    const char* wp = (const char*)smem +
                        (cb + nt * 8 + gid) * WPITCH_B + ks * 32 + 4 * tig;
                    const uint32_t h0 = *(const uint32_t*)(wp);
                    const uint32_t h1 = *(const uint32_t*)(wp + 16);
                    const uint32_t l0 = *(const uint32_t*)(wp + 9216);
                    const uint32_t l1 = *(const uint32_t*)(wp + 9216 + 16);
                    mma16816(accb[0][nt], ah0, h0, h1);
                    mma16816(accb[0][nt], ah0, l0, l1);
                    mma16816(accb[1][nt], ah1, h0, h1);
                    mma16816(accb[1][nt], ah1, l0, l1);
                }
            }
            // ---- path g (reuse fragment registers) ----
            {
                const uint32_t ad0 = sb + OFF_AG + (uint32_t)(arow0 * WPITCH_B) + chunk;
                ldm_x4(ah0, ad0);
                ldm_x4(ah1, ad0 + 16 * WPITCH_B);
                #pragma unroll
                for (int nt = 0; nt < 4; nt++) {
                    const char* wp = (const char*)smem + 18432 +
                        (cb + nt * 8 + gid) * WPITCH_B + ks * 32 + 4 * tig;
                    const uint32_t h0 = *(const uint32_t*)(wp);
                    const uint32_t h1 = *(const uint32_t*)(wp + 16);
                    const uint32_t l0 = *(const uint32_t*)(wp + 9216);
                    const uint32_t l1 = *(const uint32_t*)(wp + 9216 + 16);
                    mma16816(accg[0][nt], ah0, h0, h1);
                    mma16816(accg[0][nt], ah0, l0, l1);
                    mma16816(accg[1][nt], ah1, h0, h1);
                    mma16816(accg[1][nt], ah1, l0, l1);
                }
            }
        }

        // ---- epilogue in registers: bias + 1-MUFU gate + 32-row reduce ----
        #pragma unroll
        for (int nt = 0; nt < 4; nt++) {
            const int c0 = cb + nt * 8 + 2 * tig;
            const float2 bb = *(const float2*)(sbb2 + c0);
            const float2 gb = *(const float2*)(sbbg2 + c0);
            float p0 = 0.f, p1 = 0.f;
            #pragma unroll
            for (int s = 0; s < 2; s++) {
                p0 += (accb[s][nt][0] + bb.x) * sigmoid_t(accg[s][nt][0] + gb.x)
                    + (accb[s][nt][2] + bb.x) * sigmoid_t(accg[s][nt][2] + gb.x);
                p1 += (accb[s][nt][1] + bb.y) * sigmoid_t(accg[s][nt][1] + gb.y)
                    + (accb[s][nt][3] + bb.y) * sigmoid_t(accg[s][nt][3] + gb.y);
            }
            p0 += __shfl_xor_sync(0xFFFFFFFFu, p0, 4);
            p1 += __shfl_xor_sync(0xFFFFFFFFu, p1, 4);
            p0 += __shfl_xor_sync(0xFFFFFFFFu, p0, 8);
            p1 += __shfl_xor_sync(0xFFFFFFFFu, p1, 8);
            p0 += __shfl_xor_sync(0xFFFFFFFFu, p0, 16);
            p1 += __shfl_xor_sync(0xFFFFFFFFu, p1, 16);
            if (lane < 4)   // lanes 0..3: gid=0, tig=lane
                *(float2*)(partS + wid * 32 + nt * 8 + 2 * lane) = make_float2(p0, p1);
        }
        __syncthreads();   // sync #2

        // ---- finalize: sum 2 warp-partials per (jj,c), add U, store ----
        if (tid < 128) {
            const int jj = tid >> 6;
            const int c  = tid & 63;
            const int w1 = (c >> 5) * 4 + 2 * jj;   // ms = 2jj, nh = c>>5
            const int cl = c & 31;
            const float sum = partS[w1 * 32 + cl] + partS[(w1 + 1) * 32 + cl];
            const int o = (n * 64 + j0 + jj) * 64 + c;
            out[o] = g_U[o] + sum * (1.0f / 63.0f);
        }
        // no extra sync: partS(t+1) writes occur only after sync #1 of t+1,
        // which all finalize threads must reach first.
    }
}

// ---------------------------------------------------------------------------
// launch
// ---------------------------------------------------------------------------
extern "C" void kernel_launch(void* const* d_in, const int* in_sizes, int n_in,
                              void* d_out, int out_size)
{
    const float* x    = (const float*)d_in[0];
    const float* Wlin = (const float*)d_in[1];
    const float* blin = (const float*)d_in[2];
    const float* Wu1  = (const float*)d_in[3];
    const float* bu1  = (const float*)d_in[4];
    const float* Wu2  = (const float*)d_in[5];
    const float* bu2  = (const float*)d_in[6];
    const float* Wug1 = (const float*)d_in[7];
    const float* bug1 = (const float*)d_in[8];
    const float* Wug2 = (const float*)d_in[9];
    const float* bug2 = (const float*)d_in[10];
    const float* Wb1  = (const float*)d_in[11];
    const float* bb1  = (const float*)d_in[12];
    const float* Wb2  = (const float*)d_in[13];
    const float* bb2  = (const float*)d_in[14];
    const float* Wbg1 = (const float*)d_in[15];
    const float* bbg1 = (const float*)d_in[16];
    const float* Wbg2 = (const float*)d_in[17];
    const float* bbg2 = (const float*)d_in[18];

    float* out = (float*)d_out;

    const int prep_smem = PREP_SMEM_FLOATS * (int)sizeof(float);   // 180224 B
    cudaFuncSetAttribute(prep_kernel, cudaFuncAttributeMaxDynamicSharedMemorySize, prep_smem);
    cudaFuncSetAttribute(main_kernel, cudaFuncAttributeMaxDynamicSharedMemorySize, MAIN_SMEM_BYTES);

    prep_kernel<<<129, 512, prep_smem>>>(x, Wlin, blin, Wu1, bu1, Wu2, bu2,
                                         Wug1, bug1, Wug2, bug2,
                                         Wb1, bb1, Wbg1, bbg1, Wb2, Wbg2);
    main_kernel<<<2048, 256, MAIN_SMEM_BYTES>>>(bb2, bbg2, out);
}

// round 13
// speedup vs baseline: 1.6260x; 1.1550x over previous
#include <cuda_runtime.h>
#include <cuda_fp16.h>
#include <math.h>
#include <cstdint>

// Problem constants
#define N_ 128
#define K_ 64
#define C_ 64
#define ROWS_ (N_ * K_)   // 8192

// Scratch (device globals: no allocation allowed)
__device__ float g_U [ROWS_ * C_];   // um * ug
__device__ float g_A [ROWS_ * C_];   // h @ Wb1[:C]  + bb1
__device__ float g_B [ROWS_ * C_];   // h @ Wb1[C:]
__device__ float g_Ag[ROWS_ * C_];   // h @ Wbg1[:C] + bbg1
__device__ float g_Bg[ROWS_ * C_];   // h @ Wbg1[C:]
// Precomputed fp16 W image in exact main-kernel smem layout:
// [0,9216) Wb | [9216,18432) Wg   (c-major rows of 144 B)
__device__ unsigned char g_Wimg[18432];

__device__ __forceinline__ float tanh_fast(float x) {
    float y;
    asm("tanh.approx.f32 %0, %1;" : "=f"(y) : "f"(x));
    return y;
}
__device__ __forceinline__ uint32_t tanh_f16x2(uint32_t x) {
    uint32_t y;
    asm("tanh.approx.f16x2 %0, %1;" : "=r"(y) : "r"(x));
    return y;
}
__device__ __forceinline__ float fast_sigmoid(float x) {
    return __fdividef(1.0f, 1.0f + __expf(-x));
}
// 1-MUFU sigmoid: 0.5 + 0.5*tanh(x/2)
__device__ __forceinline__ float sigmoid_t(float x) {
    return fmaf(tanh_fast(0.5f * x), 0.5f, 0.5f);
}

// pack two fp32 into f16x2 (first arg -> low 16 bits)
__device__ __forceinline__ uint32_t pack_f16x2(float lo, float hi) {
    uint32_t r;
    asm("cvt.rn.f16x2.f32 %0, %1, %2;" : "=r"(r) : "f"(hi), "f"(lo));
    return r;
}

__device__ __forceinline__ uint32_t smem_to_u32(const void* p) {
    uint32_t a;
    asm("{ .reg .u64 t; cvta.to.shared.u64 t, %1; cvt.u32.u64 %0, t; }"
        : "=r"(a) : "l"(p));
    return a;
}

// warp-level fp16 HMMA, m16n8k16, row.col, f32 accumulate (base-target PTX)
__device__ __forceinline__ void mma16816(float acc[4], const uint32_t a[4],
                                         uint32_t b0, uint32_t b1) {
    asm volatile(
        "mma.sync.aligned.m16n8k16.row.col.f32.f16.f16.f32 "
        "{%0,%1,%2,%3}, {%4,%5,%6,%7}, {%8,%9}, {%0,%1,%2,%3};"
        : "+f"(acc[0]), "+f"(acc[1]), "+f"(acc[2]), "+f"(acc[3])
        : "r"(a[0]), "r"(a[1]), "r"(a[2]), "r"(a[3]), "r"(b0), "r"(b1));
}

__device__ __forceinline__ void ldm_x4(uint32_t r[4], uint32_t addr) {
    asm volatile(
        "ldmatrix.sync.aligned.m8n8.x4.shared.b16 {%0,%1,%2,%3}, [%4];"
        : "=r"(r[0]), "=r"(r[1]), "=r"(r[2]), "=r"(r[3]) : "r"(addr));
}

// ---------------------------------------------------------------------------
// Kernel 1 (unchanged): blocks 0..127 compute h/U/A/B/Ag/Bg, warp-autonomous
// batched GEMV. Block 128 builds the fp16 W image (hi only).
// ---------------------------------------------------------------------------
#define PREP_SMEM_FLOATS (9 * 4096 + 16 * 512)

#define GEMV4(ACC, BUF, W, BIAS)                                              \
    {                                                                         \
        ACC[0] = BIAS; ACC[1] = BIAS; ACC[2] = BIAS; ACC[3] = BIAS;           \
        _Pragma("unroll 8")                                                   \
        for (int k2 = 0; k2 < 32; k2++) {                                     \
            const float2 w0 = *(const float2*)((W) + (2 * k2)     * 64 + c0); \
            const float2 w1 = *(const float2*)((W) + (2 * k2 + 1) * 64 + c0); \
            _Pragma("unroll")                                                 \
            for (int r4 = 0; r4 < 4; r4++) {                                  \
                const float2 v = *(const float2*)((BUF) + r4 * 64 + 2 * k2);  \
                ACC[r4].x = fmaf(v.x, w0.x, fmaf(v.y, w1.x, ACC[r4].x));      \
                ACC[r4].y = fmaf(v.x, w0.y, fmaf(v.y, w1.y, ACC[r4].y));      \
            }                                                                 \
        }                                                                     \
    }

__global__ __launch_bounds__(512)
void prep_kernel(const float* __restrict__ x,
                 const float* __restrict__ Wlin, const float* __restrict__ blin,
                 const float* __restrict__ Wu1,  const float* __restrict__ bu1,
                 const float* __restrict__ Wu2,  const float* __restrict__ bu2,
                 const float* __restrict__ Wug1, const float* __restrict__ bug1,
                 const float* __restrict__ Wug2, const float* __restrict__ bug2,
                 const float* __restrict__ Wb1,  const float* __restrict__ bb1,
                 const float* __restrict__ Wbg1, const float* __restrict__ bbg1,
                 const float* __restrict__ Wb2,  const float* __restrict__ Wbg2)
{
    const int tid = threadIdx.x;

    if (blockIdx.x == 128) {
        for (int idx = tid; idx < 4096; idx += 512) {
            const int k = idx >> 6, c = idx & 63;
            const int off = c * 144 + k * 2;
            *(__half*)(g_Wimg + off)        = __float2half_rn(Wb2[idx]);
            *(__half*)(g_Wimg + 9216 + off) = __float2half_rn(Wbg2[idx]);
        }
        return;
    }

    extern __shared__ float sm[];
    float* sWlin  = sm;
    float* sWu1   = sm + 4096;
    float* sWu2   = sm + 2 * 4096;
    float* sWug1  = sm + 3 * 4096;
    float* sWug2  = sm + 4 * 4096;
    float* sWb1a  = sm + 5 * 4096;
    float* sWb1b  = sm + 6 * 4096;
    float* sWbg1a = sm + 7 * 4096;
    float* sWbg1b = sm + 8 * 4096;
    float* bufs   = sm + 9 * 4096;   // [16 warps][2][4][64]

    for (int i = tid; i < 4096; i += 512) {
        sWlin[i]  = Wlin[i];
        sWu1[i]   = Wu1[i];
        sWu2[i]   = Wu2[i];
        sWug1[i]  = Wug1[i];
        sWug2[i]  = Wug2[i];
        sWb1a[i]  = Wb1[i];
        sWb1b[i]  = Wb1[4096 + i];
        sWbg1a[i] = Wbg1[i];
        sWbg1b[i] = Wbg1[4096 + i];
    }
    __syncthreads();

    const int w    = tid >> 5;
    const int lane = tid & 31;
    const int c0   = 2 * lane;
    float* buf0 = bufs + w * 512;
    float* buf1 = buf0 + 256;
    const int row0 = blockIdx.x * 64 + w * 4;

    const float2 blin2 = *(const float2*)(blin + c0);
    const float2 bu12  = *(const float2*)(bu1  + c0);
    const float2 bu22  = *(const float2*)(bu2  + c0);
    const float2 bug12 = *(const float2*)(bug1 + c0);
    const float2 bug22 = *(const float2*)(bug2 + c0);
    const float2 bb12  = *(const float2*)(bb1  + c0);
    const float2 bbg12 = *(const float2*)(bbg1 + c0);
    const float2 zero2 = make_float2(0.f, 0.f);

    #pragma unroll
    for (int r = 0; r < 4; r++)
        *(float2*)(buf0 + r * 64 + c0) = *(const float2*)(x + (row0 + r) * 64 + c0);
    __syncwarp();

    float2 hh[4]; GEMV4(hh, buf0, sWlin, blin2);
    __syncwarp();
    #pragma unroll
    for (int r = 0; r < 4; r++) *(float2*)(buf1 + r * 64 + c0) = hh[r];
    __syncwarp();

    float2 tt[4]; GEMV4(tt, buf1, sWu1, bu12);
    #pragma unroll
    for (int r = 0; r < 4; r++) {
        tt[r].x = tanh_fast(tt[r].x); tt[r].y = tanh_fast(tt[r].y);
    }
    __syncwarp();
    #pragma unroll
    for (int r = 0; r < 4; r++) *(float2*)(buf0 + r * 64 + c0) = tt[r];
    __syncwarp();

    float2 um[4]; GEMV4(um, buf0, sWu2, bu22);

    float2 t2[4]; GEMV4(t2, buf1, sWug1, bug12);
    #pragma unroll
    for (int r = 0; r < 4; r++) {
        t2[r].x = tanh_fast(t2[r].x); t2[r].y = tanh_fast(t2[r].y);
    }
    __syncwarp();
    #pragma unroll
    for (int r = 0; r < 4; r++) *(float2*)(buf0 + r * 64 + c0) = t2[r];
    __syncwarp();

    float2 ug[4]; GEMV4(ug, buf0, sWug2, bug22);
    #pragma unroll
    for (int r = 0; r < 4; r++) {
        float2 U;
        U.x = um[r].x * fast_sigmoid(ug[r].x);
        U.y = um[r].y * fast_sigmoid(ug[r].y);
        *(float2*)(g_U + (row0 + r) * 64 + c0) = U;
    }

    float2 fa[4], fb[4], fag[4], fbg[4];
    #pragma unroll
    for (int r = 0; r < 4; r++) { fa[r] = bb12; fb[r] = zero2; fag[r] = bbg12; fbg[r] = zero2; }
    #pragma unroll 4
    for (int k2 = 0; k2 < 32; k2++) {
        const int r0 = (2 * k2) * 64 + c0, r1 = (2 * k2 + 1) * 64 + c0;
        const float2 wa0 = *(const float2*)(sWb1a  + r0);
        const float2 wa1 = *(const float2*)(sWb1a  + r1);
        const float2 wb0 = *(const float2*)(sWb1b  + r0);
        const float2 wb1 = *(const float2*)(sWb1b  + r1);
        const float2 wc0 = *(const float2*)(sWbg1a + r0);
        const float2 wc1 = *(const float2*)(sWbg1a + r1);
        const float2 wd0 = *(const float2*)(sWbg1b + r0);
        const float2 wd1 = *(const float2*)(sWbg1b + r1);
        #pragma unroll
        for (int r = 0; r < 4; r++) {
            const float2 v = *(const float2*)(buf1 + r * 64 + 2 * k2);
            fa[r].x  = fmaf(v.x, wa0.x, fmaf(v.y, wa1.x, fa[r].x));
            fa[r].y  = fmaf(v.x, wa0.y, fmaf(v.y, wa1.y, fa[r].y));
            fb[r].x  = fmaf(v.x, wb0.x, fmaf(v.y, wb1.x, fb[r].x));
            fb[r].y  = fmaf(v.x, wb0.y, fmaf(v.y, wb1.y, fb[r].y));
            fag[r].x = fmaf(v.x, wc0.x, fmaf(v.y, wc1.x, fag[r].x));
            fag[r].y = fmaf(v.x, wc0.y, fmaf(v.y, wc1.y, fag[r].y));
            fbg[r].x = fmaf(v.x, wd0.x, fmaf(v.y, wd1.x, fbg[r].x));
            fbg[r].y = fmaf(v.x, wd0.y, fmaf(v.y, wd1.y, fbg[r].y));
        }
    }
    #pragma unroll
    for (int r = 0; r < 4; r++) {
        *(float2*)(g_A  + (row0 + r) * 64 + c0) = fa[r];
        *(float2*)(g_B  + (row0 + r) * 64 + c0) = fb[r];
        *(float2*)(g_Ag + (row0 + r) * 64 + c0) = fag[r];
        *(float2*)(g_Bg + (row0 + r) * 64 + c0) = fbg[r];
    }
}

// ---------------------------------------------------------------------------
// Kernel 2 (single-pass fp16): one block per (n, 4 j's) = 2 tiles of 2 j's.
// 2048 blocks x 256 threads, 2+ CTAs/SM (smem 56.8 KB).
// A fp16 (tanh.approx.f16x2), W fp16 single image -> D = A @ W. 64 MMAs/tile
// per warp (was 128). Warp tiles 32m x 32n, both paths.
// ---------------------------------------------------------------------------
#define WPITCH_B  144
// smem: Wb [0,9216) | Wg [9216,18432) | A_b [18432,36864) | A_g [36864,55296)
#define OFF_WB    0
#define OFF_WG    9216
#define OFF_AB    18432
#define OFF_AG    36864
#define OFF_BB2   55296
#define OFF_BBG2  55552
#define OFF_PART  55808          // [8][32] floats = 1024 B
#define MAIN_SMEM_BYTES 56832

__global__ __launch_bounds__(256, 2)
void main_kernel(const float* __restrict__ bb2, const float* __restrict__ bbg2,
                 float* __restrict__ out)
{
    extern __shared__ char smem[];
    const uint32_t sb = smem_to_u32(smem);
    const int tid  = threadIdx.x;
    const int wid  = tid >> 5;
    const int lane = tid & 31;
    const int gid  = lane >> 2;
    const int tig  = lane & 3;
    const int n    = blockIdx.x >> 4;
    const int jg   = blockIdx.x & 15;

    // --- one-time: copy precomputed W image (both paths) ---
    {
        const uint4* wsrc = (const uint4*)g_Wimg;
        uint4* wdst = (uint4*)smem;
        for (int idx = tid; idx < 1152; idx += 256)
            wdst[idx] = wsrc[idx];
    }
    float* sbb2  = (float*)(smem + OFF_BB2);
    float* sbbg2 = (float*)(smem + OFF_BBG2);
    if (tid < 64) { sbb2[tid] = bb2[tid]; sbbg2[tid] = bbg2[tid]; }
    __syncthreads();

    // phase-1 mapping: (rbase, ch) — coalesced full-row loads
    const int rbase = tid >> 4;              // 0..15
    const int ch    = tid & 15;              // float4-chunk within row
    const int q1    = ch >> 1;
    const int part1 = ch & 1;
    const int swz1  = ((rbase >> 3) & 1) * 4;

    // MMA mapping: 32m x 32n warp tiles
    const int ms    = wid & 3;               // m-strip
    const int nh    = wid >> 2;              // n-half
    const int m0    = 32 * ms;
    const int cb    = 32 * nh;
    const int arow0 = m0 + (lane & 15);
    const int lsw   = ((lane >> 3) & 1) * 4;
    const int lch   = lane >> 4;

    float* partS = (float*)(smem + OFF_PART);

    for (int t = 0; t < 2; t++) {
        const int j0 = jg * 4 + 2 * t;

        // ---- phase 1: build fp16 A tiles (both paths); f16x2 tanh ----
        #pragma unroll
        for (int p = 0; p < 2; p++) {
            const float* Bsrc = (p ? g_Bg : g_B) + n * 4096;
            const float* Asrc = (p ? g_Ag : g_A) + (n * 64 + j0) * 64 + 4 * ch;
            char* hiB = smem + (p ? OFF_AG : OFF_AB);
            const float4 a0 = *(const float4*)(Asrc);
            const float4 a1 = *(const float4*)(Asrc + 64);
            #pragma unroll
            for (int c = 0; c < 4; c++) {
                const int i = 16 * c + rbase;
                const float4 b = *(const float4*)(Bsrc + i * 64 + 4 * ch);
                #pragma unroll
                for (int jj = 0; jj < 2; jj++) {
                    const float4 a = jj ? a1 : a0;
                    const int row = jj * 64 + i;
                    const uint32_t h0 = tanh_f16x2(pack_f16x2(a.x + b.x, a.y + b.y));
                    const uint32_t h1 = tanh_f16x2(pack_f16x2(a.z + b.z, a.w + b.w));
                    const int boff = row * WPITCH_B + ((q1 ^ swz1) * 16) + part1 * 8;
                    *(uint2*)(hiB + boff) = make_uint2(h0, h1);
                }
            }
        }
        __syncthreads();   // sync #1

        // ---- MMA: 32x32 warp tile, both paths, single-pass fp16 ----
        float accb[2][4][4], accg[2][4][4];
        #pragma unroll
        for (int s = 0; s < 2; s++)
            #pragma unroll
            for (int nt = 0; nt < 4; nt++)
                #pragma unroll
                for (int r = 0; r < 4; r++) { accb[s][nt][r] = 0.f; accg[s][nt][r] = 0.f; }

        #pragma unroll
        for (int ks = 0; ks < 4; ks++) {
            const uint32_t chunk = (uint32_t)(((ks * 2 + lch) ^ lsw) * 16);
            uint32_t ah0[4], ah1[4];
            // ---- path b ----
            {
                const uint32_t ad0 = sb + OFF_AB + (uint32_t)(arow0 * WPITCH_B) + chunk;
                ldm_x4(ah0, ad0);
                ldm_x4(ah1, ad0 + 16 * WPITCH_B);
                #pragma unroll
                for (int nt = 0; nt < 4; nt++) {
                    const char* wp = (const char*)smem + OFF_WB +
                        (cb + nt * 8 + gid) * WPITCH_B + ks * 32 + 4 * tig;
                    const uint32_t h0 = *(const uint32_t*)(wp);
                    const uint32_t h1 = *(const uint32_t*)(wp + 16);
                    mma16816(accb[0][nt], ah0, h0, h1);
                    mma16816(accb[1][nt], ah1, h0, h1);
                }
            }
            // ---- path g (reuse fragment registers) ----
            {
                const uint32_t ad0 = sb + OFF_AG + (uint32_t)(arow0 * WPITCH_B) + chunk;
                ldm_x4(ah0, ad0);
                ldm_x4(ah1, ad0 + 16 * WPITCH_B);
                #pragma unroll
                for (int nt = 0; nt < 4; nt++) {
                    const char* wp = (const char*)smem + OFF_WG +
                        (cb + nt * 8 + gid) * WPITCH_B + ks * 32 + 4 * tig;
                    const uint32_t h0 = *(const uint32_t*)(wp);
                    const uint32_t h1 = *(const uint32_t*)(wp + 16);
                    mma16816(accg[0][nt], ah0, h0, h1);
                    mma16816(accg[1][nt], ah1, h0, h1);
                }
            }
        }

        // ---- epilogue in registers: bias + 1-MUFU gate + 32-row reduce ----
        #pragma unroll
        for (int nt = 0; nt < 4; nt++) {
            const int c0 = cb + nt * 8 + 2 * tig;
            const float2 bb = *(const float2*)(sbb2 + c0);
            const float2 gb = *(const float2*)(sbbg2 + c0);
            float p0 = 0.f, p1 = 0.f;
            #pragma unroll
            for (int s = 0; s < 2; s++) {
                p0 += (accb[s][nt][0] + bb.x) * sigmoid_t(accg[s][nt][0] + gb.x)
                    + (accb[s][nt][2] + bb.x) * sigmoid_t(accg[s][nt][2] + gb.x);
                p1 += (accb[s][nt][1] + bb.y) * sigmoid_t(accg[s][nt][1] + gb.y)
                    + (accb[s][nt][3] + bb.y) * sigmoid_t(accg[s][nt][3] + gb.y);
            }
            p0 += __shfl_xor_sync(0xFFFFFFFFu, p0, 4);
            p1 += __shfl_xor_sync(0xFFFFFFFFu, p1, 4);
            p0 += __shfl_xor_sync(0xFFFFFFFFu, p0, 8);
            p1 += __shfl_xor_sync(0xFFFFFFFFu, p1, 8);
            p0 += __shfl_xor_sync(0xFFFFFFFFu, p0, 16);
            p1 += __shfl_xor_sync(0xFFFFFFFFu, p1, 16);
            if (lane < 4)   // lanes 0..3: gid=0, tig=lane
                *(float2*)(partS + wid * 32 + nt * 8 + 2 * lane) = make_float2(p0, p1);
        }
        __syncthreads();   // sync #2

        // ---- finalize: sum 2 warp-partials per (jj,c), add U, store ----
        if (tid < 128) {
            const int jj = tid >> 6;
            const int c  = tid & 63;
            const int w1 = (c >> 5) * 4 + 2 * jj;   // ms = 2jj, nh = c>>5
            const int cl = c & 31;
            const float sum = partS[w1 * 32 + cl] + partS[(w1 + 1) * 32 + cl];
            const int o = (n * 64 + j0 + jj) * 64 + c;
            out[o] = g_U[o] + sum * (1.0f / 63.0f);
        }
        // no extra sync: partS(t+1) writes occur only after sync #1 of t+1,
        // which all finalize threads must reach first.
    }
}

// ---------------------------------------------------------------------------
// launch
// ---------------------------------------------------------------------------
extern "C" void kernel_launch(void* const* d_in, const int* in_sizes, int n_in,
                              void* d_out, int out_size)
{
    const float* x    = (const float*)d_in[0];
    const float* Wlin = (const float*)d_in[1];
    const float* blin = (const float*)d_in[2];
    const float* Wu1  = (const float*)d_in[3];
    const float* bu1  = (const float*)d_in[4];
    const float* Wu2  = (const float*)d_in[5];
    const float* bu2  = (const float*)d_in[6];
    const float* Wug1 = (const float*)d_in[7];
    const float* bug1 = (const float*)d_in[8];
    const float* Wug2 = (const float*)d_in[9];
    const float* bug2 = (const float*)d_in[10];
    const float* Wb1  = (const float*)d_in[11];
    const float* bb1  = (const float*)d_in[12];
    const float* Wb2  = (const float*)d_in[13];
    const float* bb2  = (const float*)d_in[14];
    const float* Wbg1 = (const float*)d_in[15];
    const float* bbg1 = (const float*)d_in[16];
    const float* Wbg2 = (const float*)d_in[17];
    const float* bbg2 = (const float*)d_in[18];

    float* out = (float*)d_out;

    const int prep_smem = PREP_SMEM_FLOATS * (int)sizeof(float);   // 180224 B
    cudaFuncSetAttribute(prep_kernel, cudaFuncAttributeMaxDynamicSharedMemorySize, prep_smem);
    cudaFuncSetAttribute(main_kernel, cudaFuncAttributeMaxDynamicSharedMemorySize, MAIN_SMEM_BYTES);

    prep_kernel<<<129, 512, prep_smem>>>(x, Wlin, blin, Wu1, bu1, Wu2, bu2,
                                         Wug1, bug1, Wug2, bug2,
                                         Wb1, bb1, Wbg1, bbg1, Wb2, Wbg2);
    main_kernel<<<2048, 256, MAIN_SMEM_BYTES>>>(bb2, bbg2, out);
}

// round 14
// speedup vs baseline: 1.6374x; 1.0070x over previous
#include <cuda_runtime.h>
#include <cuda_fp16.h>
#include <math.h>
#include <cstdint>

// Problem constants
#define N_ 128
#define K_ 64
#define C_ 64
#define ROWS_ (N_ * K_)   // 8192

// Scratch (device globals: no allocation allowed)
__device__ float g_U [ROWS_ * C_];   // um * ug
__device__ float g_A [ROWS_ * C_];   // h @ Wb1[:C]  + bb1
__device__ float g_B [ROWS_ * C_];   // h @ Wb1[C:]
__device__ float g_Ag[ROWS_ * C_];   // h @ Wbg1[:C] + bbg1
__device__ float g_Bg[ROWS_ * C_];   // h @ Wbg1[C:]
// Precomputed fp16 W image in exact main-kernel smem layout:
// [0,9216) Wb | [9216,18432) Wg   (c-major rows of 144 B)
__device__ unsigned char g_Wimg[18432];

__device__ __forceinline__ float tanh_fast(float x) {
    float y;
    asm("tanh.approx.f32 %0, %1;" : "=f"(y) : "f"(x));
    return y;
}
__device__ __forceinline__ uint32_t tanh_f16x2(uint32_t x) {
    uint32_t y;
    asm("tanh.approx.f16x2 %0, %1;" : "=r"(y) : "r"(x));
    return y;
}
__device__ __forceinline__ float fast_sigmoid(float x) {
    return __fdividef(1.0f, 1.0f + __expf(-x));
}

// pack two fp32 into f16x2 (first arg -> low 16 bits)
__device__ __forceinline__ uint32_t pack_f16x2(float lo, float hi) {
    uint32_t r;
    asm("cvt.rn.f16x2.f32 %0, %1, %2;" : "=r"(r) : "f"(hi), "f"(lo));
    return r;
}

__device__ __forceinline__ uint32_t smem_to_u32(const void* p) {
    uint32_t a;
    asm("{ .reg .u64 t; cvta.to.shared.u64 t, %1; cvt.u32.u64 %0, t; }"
        : "=r"(a) : "l"(p));
    return a;
}

// warp-level fp16 HMMA, m16n8k16, row.col, f32 accumulate (base-target PTX)
__device__ __forceinline__ void mma16816(float acc[4], const uint32_t a[4],
                                         uint32_t b0, uint32_t b1) {
    asm volatile(
        "mma.sync.aligned.m16n8k16.row.col.f32.f16.f16.f32 "
        "{%0,%1,%2,%3}, {%4,%5,%6,%7}, {%8,%9}, {%0,%1,%2,%3};"
        : "+f"(acc[0]), "+f"(acc[1]), "+f"(acc[2]), "+f"(acc[3])
        : "r"(a[0]), "r"(a[1]), "r"(a[2]), "r"(a[3]), "r"(b0), "r"(b1));
}

__device__ __forceinline__ void ldm_x4(uint32_t r[4], uint32_t addr) {
    asm volatile(
        "ldmatrix.sync.aligned.m8n8.x4.shared.b16 {%0,%1,%2,%3}, [%4];"
        : "=r"(r[0]), "=r"(r[1]), "=r"(r[2]), "=r"(r[3]) : "r"(addr));
}

// ---------------------------------------------------------------------------
// Kernel 1 (unchanged from R13): blocks 0..127 compute h/U/A/B/Ag/Bg,
// warp-autonomous batched GEMV. Block 128 builds the fp16 W image.
// ---------------------------------------------------------------------------
#define PREP_SMEM_FLOATS (9 * 4096 + 16 * 512)

#define GEMV4(ACC, BUF, W, BIAS)                                              \
    {                                                                         \
        ACC[0] = BIAS; ACC[1] = BIAS; ACC[2] = BIAS; ACC[3] = BIAS;           \
        _Pragma("unroll 8")                                                   \
        for (int k2 = 0; k2 < 32; k2++) {                                     \
            const float2 w0 = *(const float2*)((W) + (2 * k2)     * 64 + c0); \
            const float2 w1 = *(const float2*)((W) + (2 * k2 + 1) * 64 + c0); \
            _Pragma("unroll")                                                 \
            for (int r4 = 0; r4 < 4; r4++) {                                  \
                const float2 v = *(const float2*)((BUF) + r4 * 64 + 2 * k2);  \
                ACC[r4].x = fmaf(v.x, w0.x, fmaf(v.y, w1.x, ACC[r4].x));      \
                ACC[r4].y = fmaf(v.x, w0.y, fmaf(v.y, w1.y, ACC[r4].y));      \
            }                                                                 \
        }                                                                     \
    }

__global__ __launch_bounds__(512)
void prep_kernel(const float* __restrict__ x,
                 const float* __restrict__ Wlin, const float* __restrict__ blin,
                 const float* __restrict__ Wu1,  const float* __restrict__ bu1,
                 const float* __restrict__ Wu2,  const float* __restrict__ bu2,
                 const float* __restrict__ Wug1, const float* __restrict__ bug1,
                 const float* __restrict__ Wug2, const float* __restrict__ bug2,
                 const float* __restrict__ Wb1,  const float* __restrict__ bb1,
                 const float* __restrict__ Wbg1, const float* __restrict__ bbg1,
                 const float* __restrict__ Wb2,  const float* __restrict__ Wbg2)
{
    const int tid = threadIdx.x;

    if (blockIdx.x == 128) {
        for (int idx = tid; idx < 4096; idx += 512) {
            const int k = idx >> 6, c = idx & 63;
            const int off = c * 144 + k * 2;
            *(__half*)(g_Wimg + off)        = __float2half_rn(Wb2[idx]);
            *(__half*)(g_Wimg + 9216 + off) = __float2half_rn(Wbg2[idx]);
        }
        return;
    }

    extern __shared__ float sm[];
    float* sWlin  = sm;
    float* sWu1   = sm + 4096;
    float* sWu2   = sm + 2 * 4096;
    float* sWug1  = sm + 3 * 4096;
    float* sWug2  = sm + 4 * 4096;
    float* sWb1a  = sm + 5 * 4096;
    float* sWb1b  = sm + 6 * 4096;
    float* sWbg1a = sm + 7 * 4096;
    float* sWbg1b = sm + 8 * 4096;
    float* bufs   = sm + 9 * 4096;   // [16 warps][2][4][64]

    for (int i = tid; i < 4096; i += 512) {
        sWlin[i]  = Wlin[i];
        sWu1[i]   = Wu1[i];
        sWu2[i]   = Wu2[i];
        sWug1[i]  = Wug1[i];
        sWug2[i]  = Wug2[i];
        sWb1a[i]  = Wb1[i];
        sWb1b[i]  = Wb1[4096 + i];
        sWbg1a[i] = Wbg1[i];
        sWbg1b[i] = Wbg1[4096 + i];
    }
    __syncthreads();

    const int w    = tid >> 5;
    const int lane = tid & 31;
    const int c0   = 2 * lane;
    float* buf0 = bufs + w * 512;
    float* buf1 = buf0 + 256;
    const int row0 = blockIdx.x * 64 + w * 4;

    const float2 blin2 = *(const float2*)(blin + c0);
    const float2 bu12  = *(const float2*)(bu1  + c0);
    const float2 bu22  = *(const float2*)(bu2  + c0);
    const float2 bug12 = *(const float2*)(bug1 + c0);
    const float2 bug22 = *(const float2*)(bug2 + c0);
    const float2 bb12  = *(const float2*)(bb1  + c0);
    const float2 bbg12 = *(const float2*)(bbg1 + c0);
    const float2 zero2 = make_float2(0.f, 0.f);

    #pragma unroll
    for (int r = 0; r < 4; r++)
        *(float2*)(buf0 + r * 64 + c0) = *(const float2*)(x + (row0 + r) * 64 + c0);
    __syncwarp();

    float2 hh[4]; GEMV4(hh, buf0, sWlin, blin2);
    __syncwarp();
    #pragma unroll
    for (int r = 0; r < 4; r++) *(float2*)(buf1 + r * 64 + c0) = hh[r];
    __syncwarp();

    float2 tt[4]; GEMV4(tt, buf1, sWu1, bu12);
    #pragma unroll
    for (int r = 0; r < 4; r++) {
        tt[r].x = tanh_fast(tt[r].x); tt[r].y = tanh_fast(tt[r].y);
    }
    __syncwarp();
    #pragma unroll
    for (int r = 0; r < 4; r++) *(float2*)(buf0 + r * 64 + c0) = tt[r];
    __syncwarp();

    float2 um[4]; GEMV4(um, buf0, sWu2, bu22);

    float2 t2[4]; GEMV4(t2, buf1, sWug1, bug12);
    #pragma unroll
    for (int r = 0; r < 4; r++) {
        t2[r].x = tanh_fast(t2[r].x); t2[r].y = tanh_fast(t2[r].y);
    }
    __syncwarp();
    #pragma unroll
    for (int r = 0; r < 4; r++) *(float2*)(buf0 + r * 64 + c0) = t2[r];
    __syncwarp();

    float2 ug[4]; GEMV4(ug, buf0, sWug2, bug22);
    #pragma unroll
    for (int r = 0; r < 4; r++) {
        float2 U;
        U.x = um[r].x * fast_sigmoid(ug[r].x);
        U.y = um[r].y * fast_sigmoid(ug[r].y);
        *(float2*)(g_U + (row0 + r) * 64 + c0) = U;
    }

    float2 fa[4], fb[4], fag[4], fbg[4];
    #pragma unroll
    for (int r = 0; r < 4; r++) { fa[r] = bb12; fb[r] = zero2; fag[r] = bbg12; fbg[r] = zero2; }
    #pragma unroll 4
    for (int k2 = 0; k2 < 32; k2++) {
        const int r0 = (2 * k2) * 64 + c0, r1 = (2 * k2 + 1) * 64 + c0;
        const float2 wa0 = *(const float2*)(sWb1a  + r0);
        const float2 wa1 = *(const float2*)(sWb1a  + r1);
        const float2 wb0 = *(const float2*)(sWb1b  + r0);
        const float2 wb1 = *(const float2*)(sWb1b  + r1);
        const float2 wc0 = *(const float2*)(sWbg1a + r0);
        const float2 wc1 = *(const float2*)(sWbg1a + r1);
        const float2 wd0 = *(const float2*)(sWbg1b + r0);
        const float2 wd1 = *(const float2*)(sWbg1b + r1);
        #pragma unroll
        for (int r = 0; r < 4; r++) {
            const float2 v = *(const float2*)(buf1 + r * 64 + 2 * k2);
            fa[r].x  = fmaf(v.x, wa0.x, fmaf(v.y, wa1.x, fa[r].x));
            fa[r].y  = fmaf(v.x, wa0.y, fmaf(v.y, wa1.y, fa[r].y));
            fb[r].x  = fmaf(v.x, wb0.x, fmaf(v.y, wb1.x, fb[r].x));
            fb[r].y  = fmaf(v.x, wb0.y, fmaf(v.y, wb1.y, fb[r].y));
            fag[r].x = fmaf(v.x, wc0.x, fmaf(v.y, wc1.x, fag[r].x));
            fag[r].y = fmaf(v.x, wc0.y, fmaf(v.y, wc1.y, fag[r].y));
            fbg[r].x = fmaf(v.x, wd0.x, fmaf(v.y, wd1.x, fbg[r].x));
            fbg[r].y = fmaf(v.x, wd0.y, fmaf(v.y, wd1.y, fbg[r].y));
        }
    }
    #pragma unroll
    for (int r = 0; r < 4; r++) {
        *(float2*)(g_A  + (row0 + r) * 64 + c0) = fa[r];
        *(float2*)(g_B  + (row0 + r) * 64 + c0) = fb[r];
        *(float2*)(g_Ag + (row0 + r) * 64 + c0) = fag[r];
        *(float2*)(g_Bg + (row0 + r) * 64 + c0) = fbg[r];
    }
}

// ---------------------------------------------------------------------------
// Kernel 2: one block per (n, 4 j's). 2048 blocks x 256 threads, 2 CTAs/SM.
// SINGLE fused build phase fills all 4 A tiles (2 tiles x 2 paths; B loaded
// once), then 2 back-to-back MMA+epilogue passes. finalize(t0) overlaps
// MMA(t1). 3 syncthreads total. f16x2 tanh everywhere (incl. gate sigmoid).
// ---------------------------------------------------------------------------
#define WPITCH_B  144
// smem: Wb [0,9216) | Wg [9216,18432) |
//       A tiles [18432 + (tile*2+path)*18432), 4 x 18432 |
//       bb2 92160 | bbg2 92416 | part0 92672 | part1 93696 | end 94720
#define OFF_WB    0
#define OFF_WG    9216
#define OFF_A     18432
#define OFF_BB2   92160
#define OFF_BBG2  92416
#define OFF_PART0 92672
#define OFF_PART1 93696
#define MAIN_SMEM_BYTES 94720

__global__ __launch_bounds__(256, 2)
void main_kernel(const float* __restrict__ bb2, const float* __restrict__ bbg2,
                 float* __restrict__ out)
{
    extern __shared__ char smem[];
    const uint32_t sb = smem_to_u32(smem);
    const int tid  = threadIdx.x;
    const int wid  = tid >> 5;
    const int lane = tid & 31;
    const int gid  = lane >> 2;
    const int tig  = lane & 3;
    const int n    = blockIdx.x >> 4;
    const int jg   = blockIdx.x & 15;

    // --- one-time: copy precomputed W image (both paths) ---
    {
        const uint4* wsrc = (const uint4*)g_Wimg;
        uint4* wdst = (uint4*)smem;
        for (int idx = tid; idx < 1152; idx += 256)
            wdst[idx] = wsrc[idx];
    }
    float* sbb2  = (float*)(smem + OFF_BB2);
    float* sbbg2 = (float*)(smem + OFF_BBG2);
    if (tid < 64) { sbb2[tid] = bb2[tid]; sbbg2[tid] = bbg2[tid]; }
    __syncthreads();

    // phase-1 mapping: (rbase, ch) — coalesced full-row loads
    const int rbase = tid >> 4;              // 0..15
    const int ch    = tid & 15;              // float4-chunk within row
    const int q1    = ch >> 1;
    const int part1 = ch & 1;
    const int swz1  = ((rbase >> 3) & 1) * 4;
    const int j0    = jg * 4;

    // MMA mapping: 32m x 32n warp tiles
    const int ms    = wid & 3;               // m-strip
    const int nh    = wid >> 2;              // n-half
    const int m0    = 32 * ms;
    const int cb    = 32 * nh;
    const int arow0 = m0 + (lane & 15);
    const int lsw   = ((lane >> 3) & 1) * 4;
    const int lch   = lane >> 4;

    // ---- fused build: all 4 A tiles (2 tiles x 2 paths), B loaded once ----
    #pragma unroll
    for (int p = 0; p < 2; p++) {
        const float* Bsrc = (p ? g_Bg : g_B) + n * 4096;
        const float* Asrc = (p ? g_Ag : g_A) + (n * 64 + j0) * 64 + 4 * ch;
        float4 aq[4];
        #pragma unroll
        for (int jj = 0; jj < 4; jj++)
            aq[jj] = *(const float4*)(Asrc + jj * 64);
        #pragma unroll
        for (int c = 0; c < 4; c++) {
            const int i = 16 * c + rbase;
            const float4 b = *(const float4*)(Bsrc + i * 64 + 4 * ch);
            #pragma unroll
            for (int jj = 0; jj < 4; jj++) {
                const int tile = jj >> 1;
                const int row  = (jj & 1) * 64 + i;
                char* dst = smem + OFF_A + (tile * 2 + p) * 18432;
                const uint32_t h0 = tanh_f16x2(pack_f16x2(aq[jj].x + b.x, aq[jj].y + b.y));
                const uint32_t h1 = tanh_f16x2(pack_f16x2(aq[jj].z + b.z, aq[jj].w + b.w));
                const int boff = row * WPITCH_B + ((q1 ^ swz1) * 16) + part1 * 8;
                *(uint2*)(dst + boff) = make_uint2(h0, h1);
            }
        }
    }
    __syncthreads();   // sync #1 (only build sync)

    #pragma unroll
    for (int tt = 0; tt < 2; tt++) {
        const uint32_t Abase = sb + OFF_A + (uint32_t)(tt * 36864);

        // ---- MMA: 32x32 warp tile, both paths, single-pass fp16 ----
        float accb[2][4][4], accg[2][4][4];
        #pragma unroll
        for (int s = 0; s < 2; s++)
            #pragma unroll
            for (int nt = 0; nt < 4; nt++)
                #pragma unroll
                for (int r = 0; r < 4; r++) { accb[s][nt][r] = 0.f; accg[s][nt][r] = 0.f; }

        #pragma unroll
        for (int ks = 0; ks < 4; ks++) {
            const uint32_t chunk = (uint32_t)(((ks * 2 + lch) ^ lsw) * 16);
            uint32_t ah0[4], ah1[4];
            // ---- path b ----
            {
                const uint32_t ad0 = Abase + (uint32_t)(arow0 * WPITCH_B) + chunk;
                ldm_x4(ah0, ad0);
                ldm_x4(ah1, ad0 + 16 * WPITCH_B);
                #pragma unroll
                for (int nt = 0; nt < 4; nt++) {
                    const char* wp = (const char*)smem + OFF_WB +
                        (cb + nt * 8 + gid) * WPITCH_B + ks * 32 + 4 * tig;
                    const uint32_t h0 = *(const uint32_t*)(wp);
                    const uint32_t h1 = *(const uint32_t*)(wp + 16);
                    mma16816(accb[0][nt], ah0, h0, h1);
                    mma16816(accb[1][nt], ah1, h0, h1);
                }
            }
            // ---- path g (reuse fragment registers) ----
            {
                const uint32_t ad0 = Abase + 18432u + (uint32_t)(arow0 * WPITCH_B) + chunk;
                ldm_x4(ah0, ad0);
                ldm_x4(ah1, ad0 + 16 * WPITCH_B);
                #pragma unroll
                for (int nt = 0; nt < 4; nt++) {
                    const char* wp = (const char*)smem + OFF_WG +
                        (cb + nt * 8 + gid) * WPITCH_B + ks * 32 + 4 * tig;
                    const uint32_t h0 = *(const uint32_t*)(wp);
                    const uint32_t h1 = *(const uint32_t*)(wp + 16);
                    mma16816(accg[0][nt], ah0, h0, h1);
                    mma16816(accg[1][nt], ah1, h0, h1);
                }
            }
        }

        // ---- epilogue: bias + f16x2-tanh gate + 32-row reduce ----
        float* partS = (float*)(smem + (tt ? OFF_PART1 : OFF_PART0));
        #pragma unroll
        for (int nt = 0; nt < 4; nt++) {
            const int c0 = cb + nt * 8 + 2 * tig;
            const float2 bb = *(const float2*)(sbb2 + c0);
            const float2 gb = *(const float2*)(sbbg2 + c0);
            float p0 = 0.f, p1 = 0.f;
            #pragma unroll
            for (int s = 0; s < 2; s++) {
                const float g0 = accg[s][nt][0] + gb.x;
                const float g1 = accg[s][nt][1] + gb.y;
                const float g2 = accg[s][nt][2] + gb.x;
                const float g3 = accg[s][nt][3] + gb.y;
                uint32_t ta = tanh_f16x2(pack_f16x2(0.5f * g0, 0.5f * g1));
                uint32_t tb = tanh_f16x2(pack_f16x2(0.5f * g2, 0.5f * g3));
                const float2 fa = __half22float2(*(__half2*)&ta);
                const float2 fb = __half22float2(*(__half2*)&tb);
                p0 += (accb[s][nt][0] + bb.x) * fmaf(fa.x, 0.5f, 0.5f)
                    + (accb[s][nt][2] + bb.x) * fmaf(fb.x, 0.5f, 0.5f);
                p1 += (accb[s][nt][1] + bb.y) * fmaf(fa.y, 0.5f, 0.5f)
                    + (accb[s][nt][3] + bb.y) * fmaf(fb.y, 0.5f, 0.5f);
            }
            p0 += __shfl_xor_sync(0xFFFFFFFFu, p0, 4);
            p1 += __shfl_xor_sync(0xFFFFFFFFu, p1, 4);
            p0 += __shfl_xor_sync(0xFFFFFFFFu, p0, 8);
            p1 += __shfl_xor_sync(0xFFFFFFFFu, p1, 8);
            p0 += __shfl_xor_sync(0xFFFFFFFFu, p0, 16);
            p1 += __shfl_xor_sync(0xFFFFFFFFu, p1, 16);
            if (lane < 4)   // lanes 0..3: gid=0, tig=lane
                *(float2*)(partS + wid * 32 + nt * 8 + 2 * lane) = make_float2(p0, p1);
        }
        __syncthreads();   // sync #2 / #3

        // ---- finalize: tid<128 writes out; tid>=128 proceeds to MMA(t1) ----
        if (tid < 128) {
            const int jj = tid >> 6;
            const int c  = tid & 63;
            const int w1 = (c >> 5) * 4 + 2 * jj;   // ms = 2jj, nh = c>>5
            const int cl = c & 31;
            const float sum = partS[w1 * 32 + cl] + partS[(w1 + 1) * 32 + cl];
            const int o = (n * 64 + j0 + 2 * tt + jj) * 64 + c;
            out[o] = g_U[o] + sum * (1.0f / 63.0f);
        }
        // safe: t1 uses partS1 (disjoint from partS0 being read); A tiles are
        // never rewritten after the single build.
    }
}

// ---------------------------------------------------------------------------
// launch
// ---------------------------------------------------------------------------
extern "C" void kernel_launch(void* const* d_in, const int* in_sizes, int n_in,
                              void* d_out, int out_size)
{
    const float* x    = (const float*)d_in[0];
    const float* Wlin = (const float*)d_in[1];
    const float* blin = (const float*)d_in[2];
    const float* Wu1  = (const float*)d_in[3];
    const float* bu1  = (const float*)d_in[4];
    const float* Wu2  = (const float*)d_in[5];
    const float* bu2  = (const float*)d_in[6];
    const float* Wug1 = (const float*)d_in[7];
    const float* bug1 = (const float*)d_in[8];
    const float* Wug2 = (const float*)d_in[9];
    const float* bug2 = (const float*)d_in[10];
    const float* Wb1  = (const float*)d_in[11];
    const float* bb1  = (const float*)d_in[12];
    const float* Wb2  = (const float*)d_in[13];
    const float* bb2  = (const float*)d_in[14];
    const float* Wbg1 = (const float*)d_in[15];
    const float* bbg1 = (const float*)d_in[16];
    const float* Wbg2 = (const float*)d_in[17];
    const float* bbg2 = (const float*)d_in[18];

    float* out = (float*)d_out;

    const int prep_smem = PREP_SMEM_FLOATS * (int)sizeof(float);   // 180224 B
    cudaFuncSetAttribute(prep_kernel, cudaFuncAttributeMaxDynamicSharedMemorySize, prep_smem);
    cudaFuncSetAttribute(main_kernel, cudaFuncAttributeMaxDynamicSharedMemorySize, MAIN_SMEM_BYTES);

    prep_kernel<<<129, 512, prep_smem>>>(x, Wlin, blin, Wu1, bu1, Wu2, bu2,
                                         Wug1, bug1, Wug2, bug2,
                                         Wb1, bb1, Wbg1, bbg1, Wb2, Wbg2);
    main_kernel<<<2048, 256, MAIN_SMEM_BYTES>>>(bb2, bbg2, out);
}

// round 15
// speedup vs baseline: 1.8131x; 1.1073x over previous
#include <cuda_runtime.h>
#include <cuda_fp16.h>
#include <math.h>
#include <cstdint>

// Problem constants
#define N_ 128
#define K_ 64
#define C_ 64
#define ROWS_ (N_ * K_)   // 8192

// Scratch (device globals: no allocation allowed)
__device__ float g_U [ROWS_ * C_];   // um * ug
__device__ float g_A [ROWS_ * C_];   // h @ Wb1[:C]  + bb1
__device__ float g_B [ROWS_ * C_];   // h @ Wb1[C:]
__device__ float g_Ag[ROWS_ * C_];   // h @ Wbg1[:C] + bbg1
__device__ float g_Bg[ROWS_ * C_];   // h @ Wbg1[C:]
// Precomputed fp16 W image for MAIN kernel: [0,9216) Wb | [9216,18432) Wg
__device__ unsigned char g_Wimg[18432];

__device__ __forceinline__ float tanh_fast(float x) {
    float y;
    asm("tanh.approx.f32 %0, %1;" : "=f"(y) : "f"(x));
    return y;
}
__device__ __forceinline__ uint32_t tanh_f16x2(uint32_t x) {
    uint32_t y;
    asm("tanh.approx.f16x2 %0, %1;" : "=r"(y) : "r"(x));
    return y;
}
__device__ __forceinline__ float fast_sigmoid(float x) {
    return __fdividef(1.0f, 1.0f + __expf(-x));
}

// pack two fp32 into f16x2 (first arg -> low 16 bits)
__device__ __forceinline__ uint32_t pack_f16x2(float lo, float hi) {
    uint32_t r;
    asm("cvt.rn.f16x2.f32 %0, %1, %2;" : "=r"(r) : "f"(hi), "f"(lo));
    return r;
}
// pack with hi/lo residual split
__device__ __forceinline__ void dpack(float v0, float v1, uint32_t& h, uint32_t& l) {
    h = pack_f16x2(v0, v1);
    const float2 f = __half22float2(*(__half2*)&h);
    l = pack_f16x2(v0 - f.x, v1 - f.y);
}

__device__ __forceinline__ uint32_t smem_to_u32(const void* p) {
    uint32_t a;
    asm("{ .reg .u64 t; cvta.to.shared.u64 t, %1; cvt.u32.u64 %0, t; }"
        : "=r"(a) : "l"(p));
    return a;
}

// warp-level fp16 HMMA, m16n8k16, row.col, f32 accumulate (base-target PTX)
__device__ __forceinline__ void mma16816(float acc[4], const uint32_t a[4],
                                         uint32_t b0, uint32_t b1) {
    asm volatile(
        "mma.sync.aligned.m16n8k16.row.col.f32.f16.f16.f32 "
        "{%0,%1,%2,%3}, {%4,%5,%6,%7}, {%8,%9}, {%0,%1,%2,%3};"
        : "+f"(acc[0]), "+f"(acc[1]), "+f"(acc[2]), "+f"(acc[3])
        : "r"(a[0]), "r"(a[1]), "r"(a[2]), "r"(a[3]), "r"(b0), "r"(b1));
}

__device__ __forceinline__ void ldm_x4(uint32_t r[4], uint32_t addr) {
    asm volatile(
        "ldmatrix.sync.aligned.m8n8.x4.shared.b16 {%0,%1,%2,%3}, [%4];"
        : "=r"(r[0]), "=r"(r[1]), "=r"(r[2]), "=r"(r[3]) : "r"(addr));
}

// ---------------------------------------------------------------------------
// Kernel 1 (tensor-core rewrite): 128 blocks x 128 threads (4 warps x 16-row
// strips). Each warp runs the full chain in registers:
//   h = x@Wlin+blin (3-pass hi/lo)         -> pack hi/lo
//   t1 = tanh(h@Wu1+bu1) (3-pass), um = t1@Wu2+bu2 (3-pass)
//   t2 = tanh(h@Wug1+bug1) (3-pass), ug = sig(t2@Wug2+bug2) (3-pass)
//   U = um*ug -> g_U
//   A/B/Ag/Bg = h@{Wb1a,Wb1b,Wbg1a,Wbg1b} (+bias) single-pass -> g_*
// D->A fragment conversion is pure in-register packing (lane layouts match).
// Block 128 builds the main kernel's fp16 W image.
// ---------------------------------------------------------------------------
#define PP 144          // W/x image pitch (bytes)
// smem offsets (each image 9216 B; _L always at +9216 from _H)
#define P_WLIN  0
#define P_WU1   18432
#define P_WU2   36864
#define P_WUG1  55296
#define P_WUG2  73728
#define P_WB1A  92160
#define P_WB1B  101376
#define P_WBG1A 110592
#define P_WBG1B 119808
#define P_XH    129024
#define P_XL    138240
#define PREP_SMEM_BYTES 147456

__global__ __launch_bounds__(128)
void prep_kernel(const float* __restrict__ x,
                 const float* __restrict__ Wlin, const float* __restrict__ blin,
                 const float* __restrict__ Wu1,  const float* __restrict__ bu1,
                 const float* __restrict__ Wu2,  const float* __restrict__ bu2,
                 const float* __restrict__ Wug1, const float* __restrict__ bug1,
                 const float* __restrict__ Wug2, const float* __restrict__ bug2,
                 const float* __restrict__ Wb1,  const float* __restrict__ bb1,
                 const float* __restrict__ Wbg1, const float* __restrict__ bbg1,
                 const float* __restrict__ Wb2,  const float* __restrict__ Wbg2)
{
    const int tid = threadIdx.x;

    // --- block 128: build fp16 W image for the MAIN kernel ---
    if (blockIdx.x == 128) {
        for (int idx = tid; idx < 4096; idx += 128) {
            const int k = idx >> 6, c = idx & 63;
            const int off = c * PP + k * 2;
            *(__half*)(g_Wimg + off)        = __float2half_rn(Wb2[idx]);
            *(__half*)(g_Wimg + 9216 + off) = __float2half_rn(Wbg2[idx]);
        }
        return;
    }

    extern __shared__ char smp[];
    const uint32_t sb = smem_to_u32(smp);

    // --- convert W matrices to fp16 images (hi/lo for unary, hi for binary) ---
    #define CVT_HL(VAL, OFF) {                                               \
        const float wv_ = (VAL);                                             \
        const __half hh_ = __float2half_rn(wv_);                             \
        *(__half*)(smp + (OFF) + off)        = hh_;                          \
        *(__half*)(smp + (OFF) + 9216 + off) =                               \
            __float2half_rn(wv_ - __half2float(hh_)); }
    for (int idx = tid; idx < 4096; idx += 128) {
        const int k = idx >> 6, c = idx & 63;
        const int off = c * PP + k * 2;
        CVT_HL(Wlin[idx], P_WLIN)
        CVT_HL(Wu1[idx],  P_WU1)
        CVT_HL(Wu2[idx],  P_WU2)
        CVT_HL(Wug1[idx], P_WUG1)
        CVT_HL(Wug2[idx], P_WUG2)
        *(__half*)(smp + P_WB1A  + off) = __float2half_rn(Wb1[idx]);
        *(__half*)(smp + P_WB1B  + off) = __float2half_rn(Wb1[4096 + idx]);
        *(__half*)(smp + P_WBG1A + off) = __float2half_rn(Wbg1[idx]);
        *(__half*)(smp + P_WBG1B + off) = __float2half_rn(Wbg1[4096 + idx]);
    }
    #undef CVT_HL

    // --- stage x rows (64 per block) as hi/lo fp16 A tiles ---
    {
        const int row  = tid >> 1;           // 0..63
        const int part = tid & 1;            // k-half
        const int swz  = ((row >> 3) & 1) * 4;
        const int row_g = blockIdx.x * 64 + row;
        #pragma unroll
        for (int qi = 0; qi < 4; qi++) {
            const int q  = part * 4 + qi;
            const int k0 = q * 8;
            const float4 v0 = *(const float4*)(x + row_g * 64 + k0);
            const float4 v1 = *(const float4*)(x + row_g * 64 + k0 + 4);
            uint32_t h0, l0, h1, l1, h2, l2, h3, l3;
            dpack(v0.x, v0.y, h0, l0);
            dpack(v0.z, v0.w, h1, l1);
            dpack(v1.x, v1.y, h2, l2);
            dpack(v1.z, v1.w, h3, l3);
            const int boff = row * PP + ((q ^ swz) * 16);
            *(uint4*)(smp + P_XH + boff) = make_uint4(h0, h1, h2, h3);
            *(uint4*)(smp + P_XL + boff) = make_uint4(l0, l1, l2, l3);
        }
    }
    __syncthreads();

    // --- per-warp chain ---
    const int w    = tid >> 5;
    const int lane = tid & 31;
    const int gid  = lane >> 2;
    const int tig  = lane & 3;
    const int arow0 = w * 16 + (lane & 15);
    const int lsw   = ((lane >> 3) & 1) * 4;
    const int lch   = lane >> 4;
    const int row_g0 = blockIdx.x * 64 + w * 16;

    // 3-pass GEMM: D += Ah@Wh + Al@Wh + Ah@Wl
    #define PGEMM3(ACC, AH, AL, WOFF)                                        \
        _Pragma("unroll")                                                    \
        for (int ks = 0; ks < 4; ks++) {                                     \
            _Pragma("unroll")                                                \
            for (int nt = 0; nt < 8; nt++) {                                 \
                const char* wp_ = smp + (WOFF) +                             \
                    (nt * 8 + gid) * PP + ks * 32 + 4 * tig;                 \
                const uint32_t wh0 = *(const uint32_t*)(wp_);                \
                const uint32_t wh1 = *(const uint32_t*)(wp_ + 16);           \
                const uint32_t wl0 = *(const uint32_t*)(wp_ + 9216);         \
                const uint32_t wl1 = *(const uint32_t*)(wp_ + 9216 + 16);    \
                mma16816(ACC[nt], AH[ks], wh0, wh1);                         \
                mma16816(ACC[nt], AL[ks], wh0, wh1);                         \
                mma16816(ACC[nt], AH[ks], wl0, wl1);                         \
            }                                                                \
        }
    #define PGEMM1(ACC, AH, WOFF)                                            \
        _Pragma("unroll")                                                    \
        for (int ks = 0; ks < 4; ks++) {                                     \
            _Pragma("unroll")                                                \
            for (int nt = 0; nt < 8; nt++) {                                 \
                const char* wp_ = smp + (WOFF) +                             \
                    (nt * 8 + gid) * PP + ks * 32 + 4 * tig;                 \
                const uint32_t wh0 = *(const uint32_t*)(wp_);                \
                const uint32_t wh1 = *(const uint32_t*)(wp_ + 16);           \
                mma16816(ACC[nt], AH[ks], wh0, wh1);                         \
            }                                                                \
        }
    #define ZACC(ACC)                                                        \
        _Pragma("unroll")                                                    \
        for (int nt = 0; nt < 8; nt++)                                       \
            _Pragma("unroll")                                                \
            for (int r = 0; r < 4; r++) ACC[nt][r] = 0.f;
    #define ADD_BIAS(ACC, BP)                                                \
        _Pragma("unroll")                                                    \
        for (int nt = 0; nt < 8; nt++) {                                     \
            const float2 bv = *(const float2*)((BP) + nt * 8 + 2 * tig);     \
            ACC[nt][0] += bv.x; ACC[nt][1] += bv.y;                          \
            ACC[nt][2] += bv.x; ACC[nt][3] += bv.y;                          \
        }
    // D -> A-fragment (hi/lo) in registers
    #define DPACK_FRAGS(AH, AL, ACC)                                         \
        _Pragma("unroll")                                                    \
        for (int ks = 0; ks < 4; ks++) {                                     \
            dpack(ACC[2*ks][0],   ACC[2*ks][1],   AH[ks][0], AL[ks][0]);     \
            dpack(ACC[2*ks][2],   ACC[2*ks][3],   AH[ks][1], AL[ks][1]);     \
            dpack(ACC[2*ks+1][0], ACC[2*ks+1][1], AH[ks][2], AL[ks][2]);     \
            dpack(ACC[2*ks+1][2], ACC[2*ks+1][3], AH[ks][3], AL[ks][3]);     \
        }
    #define TANH_ACC(ACC)                                                    \
        _Pragma("unroll")                                                    \
        for (int nt = 0; nt < 8; nt++)                                       \
            _Pragma("unroll")                                                \
            for (int r = 0; r < 4; r++) ACC[nt][r] = tanh_fast(ACC[nt][r]);
    #define STORE_ACC(ACC, GP)                                               \
        _Pragma("unroll")                                                    \
        for (int nt = 0; nt < 8; nt++) {                                     \
            const int c_ = nt * 8 + 2 * tig;                                 \
            *(float2*)((GP) + (row_g0 + gid) * 64 + c_) =                    \
                make_float2(ACC[nt][0], ACC[nt][1]);                         \
            *(float2*)((GP) + (row_g0 + gid + 8) * 64 + c_) =                \
                make_float2(ACC[nt][2], ACC[nt][3]);                         \
        }

    // x fragments
    uint32_t axh[4][4], axl[4][4];
    #pragma unroll
    for (int ks = 0; ks < 4; ks++) {
        const uint32_t ad = sb + P_XH + (uint32_t)(arow0 * PP)
                          + (uint32_t)((((ks * 2 + lch) ^ lsw)) * 16);
        ldm_x4(axh[ks], ad);
        ldm_x4(axl[ks], ad + 9216);
    }

    float acc[8][4];

    // h = x @ Wlin + blin
    ZACC(acc)
    PGEMM3(acc, axh, axl, P_WLIN)
    ADD_BIAS(acc, blin)
    uint32_t ahh[4][4], ahl[4][4];
    DPACK_FRAGS(ahh, ahl, acc)

    // t1 = tanh(h @ Wu1 + bu1)
    ZACC(acc)
    PGEMM3(acc, ahh, ahl, P_WU1)
    ADD_BIAS(acc, bu1)
    TANH_ACC(acc)
    uint32_t ath[4][4], atl[4][4];
    DPACK_FRAGS(ath, atl, acc)

    // um = t1 @ Wu2 + bu2  (kept in registers)
    float um[8][4];
    #pragma unroll
    for (int nt = 0; nt < 8; nt++)
        #pragma unroll
        for (int r = 0; r < 4; r++) um[nt][r] = 0.f;
    PGEMM3(um, ath, atl, P_WU2)
    ADD_BIAS(um, bu2)

    // t2 = tanh(h @ Wug1 + bug1)
    ZACC(acc)
    PGEMM3(acc, ahh, ahl, P_WUG1)
    ADD_BIAS(acc, bug1)
    TANH_ACC(acc)
    DPACK_FRAGS(ath, atl, acc)

    // ug = sigmoid(t2 @ Wug2 + bug2); U = um * ug
    ZACC(acc)
    PGEMM3(acc, ath, atl, P_WUG2)
    ADD_BIAS(acc, bug2)
    #pragma unroll
    for (int nt = 0; nt < 8; nt++)
        #pragma unroll
        for (int r = 0; r < 4; r++)
            acc[nt][r] = um[nt][r] * fast_sigmoid(acc[nt][r]);
    STORE_ACC(acc, g_U)

    // binary factors (single-pass fp16)
    ZACC(acc)
    PGEMM1(acc, ahh, P_WB1A)
    ADD_BIAS(acc, bb1)
    STORE_ACC(acc, g_A)

    ZACC(acc)
    PGEMM1(acc, ahh, P_WB1B)
    STORE_ACC(acc, g_B)

    ZACC(acc)
    PGEMM1(acc, ahh, P_WBG1A)
    ADD_BIAS(acc, bbg1)
    STORE_ACC(acc, g_Ag)

    ZACC(acc)
    PGEMM1(acc, ahh, P_WBG1B)
    STORE_ACC(acc, g_Bg)
}

// ---------------------------------------------------------------------------
// Kernel 2 (unchanged from R14): one block per (n, 4 j's). 2048 blocks x 256
// threads. Single fused build for all 4 A tiles, then 2 back-to-back
// MMA+epilogue passes; finalize(t0) overlaps MMA(t1). f16x2 tanh throughout.
// ---------------------------------------------------------------------------
#define WPITCH_B  144
#define OFF_WB    0
#define OFF_WG    9216
#define OFF_A     18432
#define OFF_BB2   92160
#define OFF_BBG2  92416
#define OFF_PART0 92672
#define OFF_PART1 93696
#define MAIN_SMEM_BYTES 94720

__global__ __launch_bounds__(256, 2)
void main_kernel(const float* __restrict__ bb2, const float* __restrict__ bbg2,
                 float* __restrict__ out)
{
    extern __shared__ char smem[];
    const uint32_t sb = smem_to_u32(smem);
    const int tid  = threadIdx.x;
    const int wid  = tid >> 5;
    const int lane = tid & 31;
    const int gid  = lane >> 2;
    const int tig  = lane & 3;
    const int n    = blockIdx.x >> 4;
    const int jg   = blockIdx.x & 15;

    {
        const uint4* wsrc = (const uint4*)g_Wimg;
        uint4* wdst = (uint4*)smem;
        for (int idx = tid; idx < 1152; idx += 256)
            wdst[idx] = wsrc[idx];
    }
    float* sbb2  = (float*)(smem + OFF_BB2);
    float* sbbg2 = (float*)(smem + OFF_BBG2);
    if (tid < 64) { sbb2[tid] = bb2[tid]; sbbg2[tid] = bbg2[tid]; }
    __syncthreads();

    const int rbase = tid >> 4;
    const int ch    = tid & 15;
    const int q1    = ch >> 1;
    const int part1 = ch & 1;
    const int swz1  = ((rbase >> 3) & 1) * 4;
    const int j0    = jg * 4;

    const int ms    = wid & 3;
    const int nh    = wid >> 2;
    const int m0    = 32 * ms;
    const int cb    = 32 * nh;
    const int arow0 = m0 + (lane & 15);
    const int lsw   = ((lane >> 3) & 1) * 4;
    const int lch   = lane >> 4;

    // ---- fused build: all 4 A tiles (2 tiles x 2 paths), B loaded once ----
    #pragma unroll
    for (int p = 0; p < 2; p++) {
        const float* Bsrc = (p ? g_Bg : g_B) + n * 4096;
        const float* Asrc = (p ? g_Ag : g_A) + (n * 64 + j0) * 64 + 4 * ch;
        float4 aq[4];
        #pragma unroll
        for (int jj = 0; jj < 4; jj++)
            aq[jj] = *(const float4*)(Asrc + jj * 64);
        #pragma unroll
        for (int c = 0; c < 4; c++) {
            const int i = 16 * c + rbase;
            const float4 b = *(const float4*)(Bsrc + i * 64 + 4 * ch);
            #pragma unroll
            for (int jj = 0; jj < 4; jj++) {
                const int tile = jj >> 1;
                const int row  = (jj & 1) * 64 + i;
                char* dst = smem + OFF_A + (tile * 2 + p) * 18432;
                const uint32_t h0 = tanh_f16x2(pack_f16x2(aq[jj].x + b.x, aq[jj].y + b.y));
                const uint32_t h1 = tanh_f16x2(pack_f16x2(aq[jj].z + b.z, aq[jj].w + b.w));
                const int boff = row * WPITCH_B + ((q1 ^ swz1) * 16) + part1 * 8;
                *(uint2*)(dst + boff) = make_uint2(h0, h1);
            }
        }
    }
    __syncthreads();

    #pragma unroll
    for (int tt = 0; tt < 2; tt++) {
        const uint32_t Abase = sb + OFF_A + (uint32_t)(tt * 36864);

        float accb[2][4][4], accg[2][4][4];
        #pragma unroll
        for (int s = 0; s < 2; s++)
            #pragma unroll
            for (int nt = 0; nt < 4; nt++)
                #pragma unroll
                for (int r = 0; r < 4; r++) { accb[s][nt][r] = 0.f; accg[s][nt][r] = 0.f; }

        #pragma unroll
        for (int ks = 0; ks < 4; ks++) {
            const uint32_t chunk = (uint32_t)(((ks * 2 + lch) ^ lsw) * 16);
            uint32_t ah0[4], ah1[4];
            {
                const uint32_t ad0 = Abase + (uint32_t)(arow0 * WPITCH_B) + chunk;
                ldm_x4(ah0, ad0);
                ldm_x4(ah1, ad0 + 16 * WPITCH_B);
                #pragma unroll
                for (int nt = 0; nt < 4; nt++) {
                    const char* wp = (const char*)smem + OFF_WB +
                        (cb + nt * 8 + gid) * WPITCH_B + ks * 32 + 4 * tig;
                    const uint32_t h0 = *(const uint32_t*)(wp);
                    const uint32_t h1 = *(const uint32_t*)(wp + 16);
                    mma16816(accb[0][nt], ah0, h0, h1);
                    mma16816(accb[1][nt], ah1, h0, h1);
                }
            }
            {
                const uint32_t ad0 = Abase + 18432u + (uint32_t)(arow0 * WPITCH_B) + chunk;
                ldm_x4(ah0, ad0);
                ldm_x4(ah1, ad0 + 16 * WPITCH_B);
                #pragma unroll
                for (int nt = 0; nt < 4; nt++) {
                    const char* wp = (const char*)smem + OFF_WG +
                        (cb + nt * 8 + gid) * WPITCH_B + ks * 32 + 4 * tig;
                    const uint32_t h0 = *(const uint32_t*)(wp);
                    const uint32_t h1 = *(const uint32_t*)(wp + 16);
                    mma16816(accg[0][nt], ah0, h0, h1);
                    mma16816(accg[1][nt], ah1, h0, h1);
                }
            }
        }

        float* partS = (float*)(smem + (tt ? OFF_PART1 : OFF_PART0));
        #pragma unroll
        for (int nt = 0; nt < 4; nt++) {
            const int c0 = cb + nt * 8 + 2 * tig;
            const float2 bb = *(const float2*)(sbb2 + c0);
            const float2 gb = *(const float2*)(sbbg2 + c0);
            float p0 = 0.f, p1 = 0.f;
            #pragma unroll
            for (int s = 0; s < 2; s++) {
                const float g0 = accg[s][nt][0] + gb.x;
                const float g1 = accg[s][nt][1] + gb.y;
                const float g2 = accg[s][nt][2] + gb.x;
                const float g3 = accg[s][nt][3] + gb.y;
                uint32_t ta = tanh_f16x2(pack_f16x2(0.5f * g0, 0.5f * g1));
                uint32_t tb = tanh_f16x2(pack_f16x2(0.5f * g2, 0.5f * g3));
                const float2 fa = __half22float2(*(__half2*)&ta);
                const float2 fb = __half22float2(*(__half2*)&tb);
                p0 += (accb[s][nt][0] + bb.x) * fmaf(fa.x, 0.5f, 0.5f)
                    + (accb[s][nt][2] + bb.x) * fmaf(fb.x, 0.5f, 0.5f);
                p1 += (accb[s][nt][1] + bb.y) * fmaf(fa.y, 0.5f, 0.5f)
                    + (accb[s][nt][3] + bb.y) * fmaf(fb.y, 0.5f, 0.5f);
            }
            p0 += __shfl_xor_sync(0xFFFFFFFFu, p0, 4);
            p1 += __shfl_xor_sync(0xFFFFFFFFu, p1, 4);
            p0 += __shfl_xor_sync(0xFFFFFFFFu, p0, 8);
            p1 += __shfl_xor_sync(0xFFFFFFFFu, p1, 8);
            p0 += __shfl_xor_sync(0xFFFFFFFFu, p0, 16);
            p1 += __shfl_xor_sync(0xFFFFFFFFu, p1, 16);
            if (lane < 4)
                *(float2*)(partS + wid * 32 + nt * 8 + 2 * lane) = make_float2(p0, p1);
        }
        __syncthreads();

        if (tid < 128) {
            const int jj = tid >> 6;
            const int c  = tid & 63;
            const int w1 = (c >> 5) * 4 + 2 * jj;
            const int cl = c & 31;
            const float sum = partS[w1 * 32 + cl] + partS[(w1 + 1) * 32 + cl];
            const int o = (n * 64 + j0 + 2 * tt + jj) * 64 + c;
            out[o] = g_U[o] + sum * (1.0f / 63.0f);
        }
    }
}

// ---------------------------------------------------------------------------
// launch
// ---------------------------------------------------------------------------
extern "C" void kernel_launch(void* const* d_in, const int* in_sizes, int n_in,
                              void* d_out, int out_size)
{
    const float* x    = (const float*)d_in[0];
    const float* Wlin = (const float*)d_in[1];
    const float* blin = (const float*)d_in[2];
    const float* Wu1  = (const float*)d_in[3];
    const float* bu1  = (const float*)d_in[4];
    const float* Wu2  = (const float*)d_in[5];
    const float* bu2  = (const float*)d_in[6];
    const float* Wug1 = (const float*)d_in[7];
    const float* bug1 = (const float*)d_in[8];
    const float* Wug2 = (const float*)d_in[9];
    const float* bug2 = (const float*)d_in[10];
    const float* Wb1  = (const float*)d_in[11];
    const float* bb1  = (const float*)d_in[12];
    const float* Wb2  = (const float*)d_in[13];
    const float* bb2  = (const float*)d_in[14];
    const float* Wbg1 = (const float*)d_in[15];
    const float* bbg1 = (const float*)d_in[16];
    const float* Wbg2 = (const float*)d_in[17];
    const float* bbg2 = (const float*)d_in[18];

    float* out = (float*)d_out;

    cudaFuncSetAttribute(prep_kernel, cudaFuncAttributeMaxDynamicSharedMemorySize, PREP_SMEM_BYTES);
    cudaFuncSetAttribute(main_kernel, cudaFuncAttributeMaxDynamicSharedMemorySize, MAIN_SMEM_BYTES);

    prep_kernel<<<129, 128, PREP_SMEM_BYTES>>>(x, Wlin, blin, Wu1, bu1, Wu2, bu2,
                                               Wug1, bug1, Wug2, bug2,
                                               Wb1, bb1, Wbg1, bbg1, Wb2, Wbg2);
    main_kernel<<<2048, 256, MAIN_SMEM_BYTES>>>(bb2, bbg2, out);
}

// round 16
// speedup vs baseline: 1.9935x; 1.0995x over previous
#include <cuda_runtime.h>
#include <cuda_fp16.h>
#include <math.h>
#include <cstdint>

// Problem constants
#define N_ 128
#define K_ 64
#define C_ 64
#define ROWS_ (N_ * K_)   // 8192

// Scratch (device globals: no allocation allowed)
__device__ float g_U [ROWS_ * C_];   // um * ug
__device__ float g_A [ROWS_ * C_];   // h @ Wb1[:C]  + bb1
__device__ float g_B [ROWS_ * C_];   // h @ Wb1[C:]
__device__ float g_Ag[ROWS_ * C_];   // h @ Wbg1[:C] + bbg1
__device__ float g_Bg[ROWS_ * C_];   // h @ Wbg1[C:]
// Precomputed fp16 W image for MAIN kernel: [0,9216) Wb | [9216,18432) Wg
__device__ unsigned char g_Wimg[18432];

__device__ __forceinline__ float tanh_fast(float x) {
    float y;
    asm("tanh.approx.f32 %0, %1;" : "=f"(y) : "f"(x));
    return y;
}
__device__ __forceinline__ uint32_t tanh_f16x2(uint32_t x) {
    uint32_t y;
    asm("tanh.approx.f16x2 %0, %1;" : "=r"(y) : "r"(x));
    return y;
}
__device__ __forceinline__ float fast_sigmoid(float x) {
    return __fdividef(1.0f, 1.0f + __expf(-x));
}

// pack two fp32 into f16x2 (first arg -> low 16 bits)
__device__ __forceinline__ uint32_t pack_f16x2(float lo, float hi) {
    uint32_t r;
    asm("cvt.rn.f16x2.f32 %0, %1, %2;" : "=r"(r) : "f"(hi), "f"(lo));
    return r;
}
// pack with hi/lo residual split
__device__ __forceinline__ void dpack(float v0, float v1, uint32_t& h, uint32_t& l) {
    h = pack_f16x2(v0, v1);
    const float2 f = __half22float2(*(__half2*)&h);
    l = pack_f16x2(v0 - f.x, v1 - f.y);
}

__device__ __forceinline__ uint32_t smem_to_u32(const void* p) {
    uint32_t a;
    asm("{ .reg .u64 t; cvta.to.shared.u64 t, %1; cvt.u32.u64 %0, t; }"
        : "=r"(a) : "l"(p));
    return a;
}

// warp-level fp16 HMMA, m16n8k16, row.col, f32 accumulate (base-target PTX)
__device__ __forceinline__ void mma16816(float acc[4], const uint32_t a[4],
                                         uint32_t b0, uint32_t b1) {
    asm volatile(
        "mma.sync.aligned.m16n8k16.row.col.f32.f16.f16.f32 "
        "{%0,%1,%2,%3}, {%4,%5,%6,%7}, {%8,%9}, {%0,%1,%2,%3};"
        : "+f"(acc[0]), "+f"(acc[1]), "+f"(acc[2]), "+f"(acc[3])
        : "r"(a[0]), "r"(a[1]), "r"(a[2]), "r"(a[3]), "r"(b0), "r"(b1));
}

__device__ __forceinline__ void ldm_x4(uint32_t r[4], uint32_t addr) {
    asm volatile(
        "ldmatrix.sync.aligned.m8n8.x4.shared.b16 {%0,%1,%2,%3}, [%4];"
        : "=r"(r[0]), "=r"(r[1]), "=r"(r[2]), "=r"(r[3]) : "r"(addr));
}

// ---------------------------------------------------------------------------
// Kernel 1 (tensor-core prep, R15 structure + vectorized W conversion):
// 128 blocks x 128 threads (4 warps x 16-row strips); full chain in registers.
// Block 128 builds the main kernel's fp16 W image.
// ---------------------------------------------------------------------------
#define PP 144          // W/x image pitch (bytes)
#define P_WLIN  0
#define P_WU1   18432
#define P_WU2   36864
#define P_WUG1  55296
#define P_WUG2  73728
#define P_WB1A  92160
#define P_WB1B  101376
#define P_WBG1A 110592
#define P_WBG1B 119808
#define P_XH    129024
#define P_XL    138240
#define PREP_SMEM_BYTES 147456

__global__ __launch_bounds__(128)
void prep_kernel(const float* __restrict__ x,
                 const float* __restrict__ Wlin, const float* __restrict__ blin,
                 const float* __restrict__ Wu1,  const float* __restrict__ bu1,
                 const float* __restrict__ Wu2,  const float* __restrict__ bu2,
                 const float* __restrict__ Wug1, const float* __restrict__ bug1,
                 const float* __restrict__ Wug2, const float* __restrict__ bug2,
                 const float* __restrict__ Wb1,  const float* __restrict__ bb1,
                 const float* __restrict__ Wbg1, const float* __restrict__ bbg1,
                 const float* __restrict__ Wb2,  const float* __restrict__ Wbg2)
{
    const int tid = threadIdx.x;

    // --- block 128: build fp16 W image for the MAIN kernel (vectorized) ---
    if (blockIdx.x == 128) {
        for (int tq = tid; tq < 1024; tq += 128) {
            const int c  = tq & 63;
            const int kb = (tq >> 6) * 4;
            const int off = c * PP + kb * 2;
            {
                const uint32_t h0 = pack_f16x2(Wb2[(kb + 0) * 64 + c], Wb2[(kb + 1) * 64 + c]);
                const uint32_t h1 = pack_f16x2(Wb2[(kb + 2) * 64 + c], Wb2[(kb + 3) * 64 + c]);
                *(uint2*)(g_Wimg + off) = make_uint2(h0, h1);
            }
            {
                const uint32_t h0 = pack_f16x2(Wbg2[(kb + 0) * 64 + c], Wbg2[(kb + 1) * 64 + c]);
                const uint32_t h1 = pack_f16x2(Wbg2[(kb + 2) * 64 + c], Wbg2[(kb + 3) * 64 + c]);
                *(uint2*)(g_Wimg + 9216 + off) = make_uint2(h0, h1);
            }
        }
        return;
    }

    extern __shared__ char smp[];
    const uint32_t sb = smem_to_u32(smp);

    // --- vectorized W conversion: thread owns (c, k-quad) ---
    #define CVT4_HL(SRC, OFF) {                                              \
        uint32_t h0_, l0_, h1_, l1_;                                         \
        dpack((SRC)[(kb + 0) * 64 + c], (SRC)[(kb + 1) * 64 + c], h0_, l0_); \
        dpack((SRC)[(kb + 2) * 64 + c], (SRC)[(kb + 3) * 64 + c], h1_, l1_); \
        *(uint2*)(smp + (OFF) + off)        = make_uint2(h0_, h1_);          \
        *(uint2*)(smp + (OFF) + 9216 + off) = make_uint2(l0_, l1_); }
    #define CVT4_H(SRC, BASEOFF, OFF) {                                      \
        const uint32_t h0_ = pack_f16x2((SRC)[(BASEOFF) + (kb + 0) * 64 + c],\
                                        (SRC)[(BASEOFF) + (kb + 1) * 64 + c]);\
        const uint32_t h1_ = pack_f16x2((SRC)[(BASEOFF) + (kb + 2) * 64 + c],\
                                        (SRC)[(BASEOFF) + (kb + 3) * 64 + c]);\
        *(uint2*)(smp + (OFF) + off) = make_uint2(h0_, h1_); }
    for (int tq = tid; tq < 1024; tq += 128) {
        const int c  = tq & 63;
        const int kb = (tq >> 6) * 4;
        const int off = c * PP + kb * 2;
        CVT4_HL(Wlin, P_WLIN)
        CVT4_HL(Wu1,  P_WU1)
        CVT4_HL(Wu2,  P_WU2)
        CVT4_HL(Wug1, P_WUG1)
        CVT4_HL(Wug2, P_WUG2)
        CVT4_H(Wb1,  0,    P_WB1A)
        CVT4_H(Wb1,  4096, P_WB1B)
        CVT4_H(Wbg1, 0,    P_WBG1A)
        CVT4_H(Wbg1, 4096, P_WBG1B)
    }
    #undef CVT4_HL
    #undef CVT4_H

    // --- stage x rows (64 per block) as hi/lo fp16 A tiles ---
    {
        const int row  = tid >> 1;           // 0..63
        const int part = tid & 1;            // k-half
        const int swz  = ((row >> 3) & 1) * 4;
        const int row_g = blockIdx.x * 64 + row;
        #pragma unroll
        for (int qi = 0; qi < 4; qi++) {
            const int q  = part * 4 + qi;
            const int k0 = q * 8;
            const float4 v0 = *(const float4*)(x + row_g * 64 + k0);
            const float4 v1 = *(const float4*)(x + row_g * 64 + k0 + 4);
            uint32_t h0, l0, h1, l1, h2, l2, h3, l3;
            dpack(v0.x, v0.y, h0, l0);
            dpack(v0.z, v0.w, h1, l1);
            dpack(v1.x, v1.y, h2, l2);
            dpack(v1.z, v1.w, h3, l3);
            const int boff = row * PP + ((q ^ swz) * 16);
            *(uint4*)(smp + P_XH + boff) = make_uint4(h0, h1, h2, h3);
            *(uint4*)(smp + P_XL + boff) = make_uint4(l0, l1, l2, l3);
        }
    }
    __syncthreads();

    // --- per-warp chain ---
    const int w    = tid >> 5;
    const int lane = tid & 31;
    const int gid  = lane >> 2;
    const int tig  = lane & 3;
    const int arow0 = w * 16 + (lane & 15);
    const int lsw   = ((lane >> 3) & 1) * 4;
    const int lch   = lane >> 4;
    const int row_g0 = blockIdx.x * 64 + w * 16;

    #define PGEMM3(ACC, AH, AL, WOFF)                                        \
        _Pragma("unroll")                                                    \
        for (int ks = 0; ks < 4; ks++) {                                     \
            _Pragma("unroll")                                                \
            for (int nt = 0; nt < 8; nt++) {                                 \
                const char* wp_ = smp + (WOFF) +                             \
                    (nt * 8 + gid) * PP + ks * 32 + 4 * tig;                 \
                const uint32_t wh0 = *(const uint32_t*)(wp_);                \
                const uint32_t wh1 = *(const uint32_t*)(wp_ + 16);           \
                const uint32_t wl0 = *(const uint32_t*)(wp_ + 9216);         \
                const uint32_t wl1 = *(const uint32_t*)(wp_ + 9216 + 16);    \
                mma16816(ACC[nt], AH[ks], wh0, wh1);                         \
                mma16816(ACC[nt], AL[ks], wh0, wh1);                         \
                mma16816(ACC[nt], AH[ks], wl0, wl1);                         \
            }                                                                \
        }
    #define PGEMM1(ACC, AH, WOFF)                                            \
        _Pragma("unroll")                                                    \
        for (int ks = 0; ks < 4; ks++) {                                     \
            _Pragma("unroll")                                                \
            for (int nt = 0; nt < 8; nt++) {                                 \
                const char* wp_ = smp + (WOFF) +                             \
                    (nt * 8 + gid) * PP + ks * 32 + 4 * tig;                 \
                const uint32_t wh0 = *(const uint32_t*)(wp_);                \
                const uint32_t wh1 = *(const uint32_t*)(wp_ + 16);           \
                mma16816(ACC[nt], AH[ks], wh0, wh1);                         \
            }                                                                \
        }
    #define ZACC(ACC)                                                        \
        _Pragma("unroll")                                                    \
        for (int nt = 0; nt < 8; nt++)                                       \
            _Pragma("unroll")                                                \
            for (int r = 0; r < 4; r++) ACC[nt][r] = 0.f;
    #define ADD_BIAS(ACC, BP)                                                \
        _Pragma("unroll")                                                    \
        for (int nt = 0; nt < 8; nt++) {                                     \
            const float2 bv = *(const float2*)((BP) + nt * 8 + 2 * tig);     \
            ACC[nt][0] += bv.x; ACC[nt][1] += bv.y;                          \
            ACC[nt][2] += bv.x; ACC[nt][3] += bv.y;                          \
        }
    #define DPACK_FRAGS(AH, AL, ACC)                                         \
        _Pragma("unroll")                                                    \
        for (int ks = 0; ks < 4; ks++) {                                     \
            dpack(ACC[2*ks][0],   ACC[2*ks][1],   AH[ks][0], AL[ks][0]);     \
            dpack(ACC[2*ks][2],   ACC[2*ks][3],   AH[ks][1], AL[ks][1]);     \
            dpack(ACC[2*ks+1][0], ACC[2*ks+1][1], AH[ks][2], AL[ks][2]);     \
            dpack(ACC[2*ks+1][2], ACC[2*ks+1][3], AH[ks][3], AL[ks][3]);     \
        }
    #define TANH_ACC(ACC)                                                    \
        _Pragma("unroll")                                                    \
        for (int nt = 0; nt < 8; nt++)                                       \
            _Pragma("unroll")                                                \
            for (int r = 0; r < 4; r++) ACC[nt][r] = tanh_fast(ACC[nt][r]);
    #define STORE_ACC(ACC, GP)                                               \
        _Pragma("unroll")                                                    \
        for (int nt = 0; nt < 8; nt++) {                                     \
            const int c_ = nt * 8 + 2 * tig;                                 \
            *(float2*)((GP) + (row_g0 + gid) * 64 + c_) =                    \
                make_float2(ACC[nt][0], ACC[nt][1]);                         \
            *(float2*)((GP) + (row_g0 + gid + 8) * 64 + c_) =                \
                make_float2(ACC[nt][2], ACC[nt][3]);                         \
        }

    uint32_t axh[4][4], axl[4][4];
    #pragma unroll
    for (int ks = 0; ks < 4; ks++) {
        const uint32_t ad = sb + P_XH + (uint32_t)(arow0 * PP)
                          + (uint32_t)((((ks * 2 + lch) ^ lsw)) * 16);
        ldm_x4(axh[ks], ad);
        ldm_x4(axl[ks], ad + 9216);
    }

    float acc[8][4];

    ZACC(acc)
    PGEMM3(acc, axh, axl, P_WLIN)
    ADD_BIAS(acc, blin)
    uint32_t ahh[4][4], ahl[4][4];
    DPACK_FRAGS(ahh, ahl, acc)

    ZACC(acc)
    PGEMM3(acc, ahh, ahl, P_WU1)
    ADD_BIAS(acc, bu1)
    TANH_ACC(acc)
    uint32_t ath[4][4], atl[4][4];
    DPACK_FRAGS(ath, atl, acc)

    float um[8][4];
    #pragma unroll
    for (int nt = 0; nt < 8; nt++)
        #pragma unroll
        for (int r = 0; r < 4; r++) um[nt][r] = 0.f;
    PGEMM3(um, ath, atl, P_WU2)
    ADD_BIAS(um, bu2)

    ZACC(acc)
    PGEMM3(acc, ahh, ahl, P_WUG1)
    ADD_BIAS(acc, bug1)
    TANH_ACC(acc)
    DPACK_FRAGS(ath, atl, acc)

    ZACC(acc)
    PGEMM3(acc, ath, atl, P_WUG2)
    ADD_BIAS(acc, bug2)
    #pragma unroll
    for (int nt = 0; nt < 8; nt++)
        #pragma unroll
        for (int r = 0; r < 4; r++)
            acc[nt][r] = um[nt][r] * fast_sigmoid(acc[nt][r]);
    STORE_ACC(acc, g_U)

    ZACC(acc)
    PGEMM1(acc, ahh, P_WB1A)
    ADD_BIAS(acc, bb1)
    STORE_ACC(acc, g_A)

    ZACC(acc)
    PGEMM1(acc, ahh, P_WB1B)
    STORE_ACC(acc, g_B)

    ZACC(acc)
    PGEMM1(acc, ahh, P_WBG1A)
    ADD_BIAS(acc, bbg1)
    STORE_ACC(acc, g_Ag)

    ZACC(acc)
    PGEMM1(acc, ahh, P_WBG1B)
    STORE_ACC(acc, g_Bg)
}

// ---------------------------------------------------------------------------
// Kernel 2 (R15 structure + fused prologue): one block per (n, 4 j's).
// 2048 blocks x 256 threads. W-copy + bias-copy + U-prefetch + fused 4-tile
// build all before ONE sync, then 2 back-to-back MMA+epilogue passes.
// ---------------------------------------------------------------------------
#define WPITCH_B  144
#define OFF_WB    0
#define OFF_WG    9216
#define OFF_A     18432
#define OFF_BB2   92160
#define OFF_BBG2  92416
#define OFF_PART0 92672
#define OFF_PART1 93696
#define MAIN_SMEM_BYTES 94720

__global__ __launch_bounds__(256, 2)
void main_kernel(const float* __restrict__ bb2, const float* __restrict__ bbg2,
                 float* __restrict__ out)
{
    extern __shared__ char smem[];
    const uint32_t sb = smem_to_u32(smem);
    const int tid  = threadIdx.x;
    const int wid  = tid >> 5;
    const int lane = tid & 31;
    const int gid  = lane >> 2;
    const int tig  = lane & 3;
    const int n    = blockIdx.x >> 4;
    const int jg   = blockIdx.x & 15;
    const int j0   = jg * 4;

    // ---- fused prologue (no sync until everything staged) ----
    // W image copy
    {
        const uint4* wsrc = (const uint4*)g_Wimg;
        uint4* wdst = (uint4*)smem;
        for (int idx = tid; idx < 1152; idx += 256)
            wdst[idx] = wsrc[idx];
    }
    // biases
    float* sbb2  = (float*)(smem + OFF_BB2);
    float* sbbg2 = (float*)(smem + OFF_BBG2);
    if (tid < 64) { sbb2[tid] = bb2[tid]; sbbg2[tid] = bbg2[tid]; }
    // U prefetch (finalize threads)
    float uPre0 = 0.f, uPre1 = 0.f;
    int oIdx0 = 0, oIdx1 = 0;
    if (tid < 128) {
        const int jj = tid >> 6;
        const int c  = tid & 63;
        oIdx0 = (n * 64 + j0 + 0 + jj) * 64 + c;
        oIdx1 = (n * 64 + j0 + 2 + jj) * 64 + c;
        uPre0 = g_U[oIdx0];
        uPre1 = g_U[oIdx1];
    }
    // fused build: all 4 A tiles (2 tiles x 2 paths), B loaded once
    {
        const int rbase = tid >> 4;
        const int ch    = tid & 15;
        const int q1    = ch >> 1;
        const int part1 = ch & 1;
        const int swz1  = ((rbase >> 3) & 1) * 4;
        #pragma unroll
        for (int p = 0; p < 2; p++) {
            const float* Bsrc = (p ? g_Bg : g_B) + n * 4096;
            const float* Asrc = (p ? g_Ag : g_A) + (n * 64 + j0) * 64 + 4 * ch;
            float4 aq[4];
            #pragma unroll
            for (int jj = 0; jj < 4; jj++)
                aq[jj] = *(const float4*)(Asrc + jj * 64);
            #pragma unroll
            for (int c = 0; c < 4; c++) {
                const int i = 16 * c + rbase;
                const float4 b = *(const float4*)(Bsrc + i * 64 + 4 * ch);
                #pragma unroll
                for (int jj = 0; jj < 4; jj++) {
                    const int tile = jj >> 1;
                    const int row  = (jj & 1) * 64 + i;
                    char* dst = smem + OFF_A + (tile * 2 + p) * 18432;
                    const uint32_t h0 = tanh_f16x2(pack_f16x2(aq[jj].x + b.x, aq[jj].y + b.y));
                    const uint32_t h1 = tanh_f16x2(pack_f16x2(aq[jj].z + b.z, aq[jj].w + b.w));
                    const int boff = row * WPITCH_B + ((q1 ^ swz1) * 16) + part1 * 8;
                    *(uint2*)(dst + boff) = make_uint2(h0, h1);
                }
            }
        }
    }
    __syncthreads();   // single prologue sync

    // MMA mapping: 32m x 32n warp tiles
    const int ms    = wid & 3;
    const int nh    = wid >> 2;
    const int m0    = 32 * ms;
    const int cb    = 32 * nh;
    const int arow0 = m0 + (lane & 15);
    const int lsw   = ((lane >> 3) & 1) * 4;
    const int lch   = lane >> 4;

    #pragma unroll
    for (int tt = 0; tt < 2; tt++) {
        const uint32_t Abase = sb + OFF_A + (uint32_t)(tt * 36864);

        float accb[2][4][4], accg[2][4][4];
        #pragma unroll
        for (int s = 0; s < 2; s++)
            #pragma unroll
            for (int nt = 0; nt < 4; nt++)
                #pragma unroll
                for (int r = 0; r < 4; r++) { accb[s][nt][r] = 0.f; accg[s][nt][r] = 0.f; }

        #pragma unroll
        for (int ks = 0; ks < 4; ks++) {
            const uint32_t chunk = (uint32_t)(((ks * 2 + lch) ^ lsw) * 16);
            uint32_t ah0[4], ah1[4];
            {
                const uint32_t ad0 = Abase + (uint32_t)(arow0 * WPITCH_B) + chunk;
                ldm_x4(ah0, ad0);
                ldm_x4(ah1, ad0 + 16 * WPITCH_B);
                #pragma unroll
                for (int nt = 0; nt < 4; nt++) {
                    const char* wp = (const char*)smem + OFF_WB +
                        (cb + nt * 8 + gid) * WPITCH_B + ks * 32 + 4 * tig;
                    const uint32_t h0 = *(const uint32_t*)(wp);
                    const uint32_t h1 = *(const uint32_t*)(wp + 16);
                    mma16816(accb[0][nt], ah0, h0, h1);
                    mma16816(accb[1][nt], ah1, h0, h1);
                }
            }
            {
                const uint32_t ad0 = Abase + 18432u + (uint32_t)(arow0 * WPITCH_B) + chunk;
                ldm_x4(ah0, ad0);
                ldm_x4(ah1, ad0 + 16 * WPITCH_B);
                #pragma unroll
                for (int nt = 0; nt < 4; nt++) {
                    const char* wp = (const char*)smem + OFF_WG +
                        (cb + nt * 8 + gid) * WPITCH_B + ks * 32 + 4 * tig;
                    const uint32_t h0 = *(const uint32_t*)(wp);
                    const uint32_t h1 = *(const uint32_t*)(wp + 16);
                    mma16816(accg[0][nt], ah0, h0, h1);
                    mma16816(accg[1][nt], ah1, h0, h1);
                }
            }
        }

        float* partS = (float*)(smem + (tt ? OFF_PART1 : OFF_PART0));
        #pragma unroll
        for (int nt = 0; nt < 4; nt++) {
            const int c0 = cb + nt * 8 + 2 * tig;
            const float2 bb = *(const float2*)(sbb2 + c0);
            const float2 gb = *(const float2*)(sbbg2 + c0);
            float p0 = 0.f, p1 = 0.f;
            #pragma unroll
            for (int s = 0; s < 2; s++) {
                const float g0 = accg[s][nt][0] + gb.x;
                const float g1 = accg[s][nt][1] + gb.y;
                const float g2 = accg[s][nt][2] + gb.x;
                const float g3 = accg[s][nt][3] + gb.y;
                uint32_t ta = tanh_f16x2(pack_f16x2(0.5f * g0, 0.5f * g1));
                uint32_t tb = tanh_f16x2(pack_f16x2(0.5f * g2, 0.5f * g3));
                const float2 fa = __half22float2(*(__half2*)&ta);
                const float2 fb = __half22float2(*(__half2*)&tb);
                p0 += (accb[s][nt][0] + bb.x) * fmaf(fa.x, 0.5f, 0.5f)
                    + (accb[s][nt][2] + bb.x) * fmaf(fb.x, 0.5f, 0.5f);
                p1 += (accb[s][nt][1] + bb.y) * fmaf(fa.y, 0.5f, 0.5f)
                    + (accb[s][nt][3] + bb.y) * fmaf(fb.y, 0.5f, 0.5f);
            }
            p0 += __shfl_xor_sync(0xFFFFFFFFu, p0, 4);
            p1 += __shfl_xor_sync(0xFFFFFFFFu, p1, 4);
            p0 += __shfl_xor_sync(0xFFFFFFFFu, p0, 8);
            p1 += __shfl_xor_sync(0xFFFFFFFFu, p1, 8);
            p0 += __shfl_xor_sync(0xFFFFFFFFu, p0, 16);
            p1 += __shfl_xor_sync(0xFFFFFFFFu, p1, 16);
            if (lane < 4)
                *(float2*)(partS + wid * 32 + nt * 8 + 2 * lane) = make_float2(p0, p1);
        }
        __syncthreads();

        if (tid < 128) {
            const int jj = tid >> 6;
            const int c  = tid & 63;
            const int w1 = (c >> 5) * 4 + 2 * jj;
            const int cl = c & 31;
            const float sum = partS[w1 * 32 + cl] + partS[(w1 + 1) * 32 + cl];
            if (tt == 0) out[oIdx0] = uPre0 + sum * (1.0f / 63.0f);
            else         out[oIdx1] = uPre1 + sum * (1.0f / 63.0f);
        }
    }
}

// ---------------------------------------------------------------------------
// launch
// ---------------------------------------------------------------------------
extern "C" void kernel_launch(void* const* d_in, const int* in_sizes, int n_in,
                              void* d_out, int out_size)
{
    const float* x    = (const float*)d_in[0];
    const float* Wlin = (const float*)d_in[1];
    const float* blin = (const float*)d_in[2];
    const float* Wu1  = (const float*)d_in[3];
    const float* bu1  = (const float*)d_in[4];
    const float* Wu2  = (const float*)d_in[5];
    const float* bu2  = (const float*)d_in[6];
    const float* Wug1 = (const float*)d_in[7];
    const float* bug1 = (const float*)d_in[8];
    const float* Wug2 = (const float*)d_in[9];
    const float* bug2 = (const float*)d_in[10];
    const float* Wb1  = (const float*)d_in[11];
    const float* bb1  = (const float*)d_in[12];
    const float* Wb2  = (const float*)d_in[13];
    const float* bb2  = (const float*)d_in[14];
    const float* Wbg1 = (const float*)d_in[15];
    const float* bbg1 = (const float*)d_in[16];
    const float* Wbg2 = (const float*)d_in[17];
    const float* bbg2 = (const float*)d_in[18];

    float* out = (float*)d_out;

    cudaFuncSetAttribute(prep_kernel, cudaFuncAttributeMaxDynamicSharedMemorySize, PREP_SMEM_BYTES);
    cudaFuncSetAttribute(main_kernel, cudaFuncAttributeMaxDynamicSharedMemorySize, MAIN_SMEM_BYTES);

    prep_kernel<<<129, 128, PREP_SMEM_BYTES>>>(x, Wlin, blin, Wu1, bu1, Wu2, bu2,
                                               Wug1, bug1, Wug2, bug2,
                                               Wb1, bb1, Wbg1, bbg1, Wb2, Wbg2);
    main_kernel<<<2048, 256, MAIN_SMEM_BYTES>>>(bb2, bbg2, out);
}